// round 1
// baseline (speedup 1.0000x reference)
#include <cuda_runtime.h>
#include <math.h>

// ---------------------------------------------------------------------------
// DN4Fast: Conv64F encoder (4x conv-bn-lrelu, 2x maxpool) on 80 images,
// L2-normalized local descriptors, cosine-sim top-3 scores.
// Shapes: query (2,15,3,84,84) -> 30 imgs; support (2,5,5,3,84,84) -> 50 imgs.
// Encoder out (N,64,21,21). Scores (30,5).
// ---------------------------------------------------------------------------

#define NIMG   80
#define NQIMG  30           // first 30 images are query batch (BN group 0)
#define S1     84
#define S2     42
#define S3     21
#define DCH    64
#define HW3    (S3*S3)      // 441
#define MDIM   (5*HW3)      // 2205 (Shot * hw)
#define LRELU_SLOPE 0.2f

// scratch buffers (static device memory; no allocation)
__device__ float g_buf1[(size_t)NIMG*DCH*S1*S1];  // conv1 out
__device__ float g_buf2[(size_t)NIMG*DCH*S2*S2];  // pool1 out
__device__ float g_buf3[(size_t)NIMG*DCH*S2*S2];  // conv2 out
__device__ float g_buf4[(size_t)NIMG*DCH*S3*S3];  // pool2 out
__device__ float g_buf5[(size_t)NIMG*DCH*S3*S3];  // conv3 out
__device__ float g_buf6[(size_t)NIMG*DCH*S3*S3];  // feat3
__device__ float g_buf7[(size_t)NIMG*DCH*S3*S3];  // conv4 out
__device__ float g_buf8[(size_t)NIMG*DCH*S3*S3];  // feat4
__device__ float g_qdesc[(size_t)NQIMG*HW3*DCH];  // (30,441,64)
__device__ float g_sdesc[(size_t)10*MDIM*DCH];    // (10,2205,64)
__device__ float g_bnA[2*DCH];                    // per (group,channel) scale
__device__ float g_bnC[2*DCH];                    // per (group,channel) shift

// ---------------------------------------------------------------------------
// conv1: 3 -> 64, 84x84, SAME. One thread per output pixel.
// ---------------------------------------------------------------------------
__global__ void conv1_kernel(const float* __restrict__ q,
                             const float* __restrict__ s,
                             const float* __restrict__ W1) {
    int p = blockIdx.x * blockDim.x + threadIdx.x;
    if (p >= S1 * S1) return;
    int co = blockIdx.y;
    int n  = blockIdx.z;
    int y = p / S1, x = p % S1;
    const float* img = (n < NQIMG) ? q + (size_t)n * 3 * S1 * S1
                                   : s + (size_t)(n - NQIMG) * 3 * S1 * S1;
    float wr[27];
#pragma unroll
    for (int i = 0; i < 27; i++) wr[i] = __ldg(&W1[co * 27 + i]);
    float acc = 0.f;
#pragma unroll
    for (int ci = 0; ci < 3; ci++) {
        const float* ip = img + ci * S1 * S1;
#pragma unroll
        for (int ky = 0; ky < 3; ky++) {
            int yy = y + ky - 1;
            if ((unsigned)yy >= S1) continue;
#pragma unroll
            for (int kx = 0; kx < 3; kx++) {
                int xx = x + kx - 1;
                if ((unsigned)xx >= S1) continue;
                acc += ip[yy * S1 + xx] * wr[ci * 9 + ky * 3 + kx];
            }
        }
    }
    g_buf1[((size_t)n * DCH + co) * (S1 * S1) + p] = acc;
}

// ---------------------------------------------------------------------------
// conv 64->64, SxS, SAME. Block: (co_group of 4, image). 256 threads.
// Input plane (+halo) staged in smem per input channel.
// STAGE: 0 buf2->buf3 (S=42), 1 buf4->buf5 (S=21), 2 buf6->buf7 (S=21)
// ---------------------------------------------------------------------------
template <int S, int STAGE>
__global__ void conv64_kernel(const float* __restrict__ W) {
    constexpr int SS  = S * S;
    constexpr int SP  = S + 2;
    constexpr int PPT = (SS + 255) / 256;
    const float* in = (STAGE == 0) ? g_buf2 : (STAGE == 1) ? g_buf4 : g_buf6;
    float*      out = (STAGE == 0) ? g_buf3 : (STAGE == 1) ? g_buf5 : g_buf7;

    __shared__ float plane[SP * SP];
    __shared__ float ws[4 * 64 * 9];

    int cog = blockIdx.x;     // 0..15
    int n   = blockIdx.y;
    int tid = threadIdx.x;

    for (int i = tid; i < 2304; i += 256) ws[i] = W[cog * 2304 + i];

    float acc[PPT][4];
#pragma unroll
    for (int pp = 0; pp < PPT; pp++)
#pragma unroll
        for (int c = 0; c < 4; c++) acc[pp][c] = 0.f;

    const float* ibase = in + (size_t)n * DCH * SS;

    for (int ci = 0; ci < DCH; ci++) {
        __syncthreads();
        for (int i = tid; i < SP * SP; i += 256) {
            int yy = i / SP - 1, xx = i % SP - 1;
            plane[i] = ((unsigned)yy < S && (unsigned)xx < S)
                           ? ibase[ci * SS + yy * S + xx] : 0.f;
        }
        __syncthreads();

        float w0[9], w1[9], w2[9], w3[9];
#pragma unroll
        for (int k = 0; k < 9; k++) {
            w0[k] = ws[0 * 576 + ci * 9 + k];
            w1[k] = ws[1 * 576 + ci * 9 + k];
            w2[k] = ws[2 * 576 + ci * 9 + k];
            w3[k] = ws[3 * 576 + ci * 9 + k];
        }
#pragma unroll
        for (int pp = 0; pp < PPT; pp++) {
            int p = tid + pp * 256;
            if (p < SS) {
                int y = p / S, x = p % S;
                const float* pc = &plane[y * SP + x];
                float sv[9];
#pragma unroll
                for (int dy = 0; dy < 3; dy++)
#pragma unroll
                    for (int dx = 0; dx < 3; dx++)
                        sv[dy * 3 + dx] = pc[dy * SP + dx];
#pragma unroll
                for (int k = 0; k < 9; k++) {
                    acc[pp][0] += sv[k] * w0[k];
                    acc[pp][1] += sv[k] * w1[k];
                    acc[pp][2] += sv[k] * w2[k];
                    acc[pp][3] += sv[k] * w3[k];
                }
            }
        }
    }
#pragma unroll
    for (int pp = 0; pp < PPT; pp++) {
        int p = tid + pp * 256;
        if (p < SS)
#pragma unroll
            for (int c = 0; c < 4; c++)
                out[((size_t)n * DCH + cog * 4 + c) * SS + p] = acc[pp][c];
    }
}

// ---------------------------------------------------------------------------
// BN statistics per (group, channel). group 0 = imgs [0,30), 1 = [30,80).
// STAGE selects input buffer: 0 buf1(84), 1 buf3(42), 2 buf5(21), 3 buf7(21)
// ---------------------------------------------------------------------------
template <int STAGE>
__global__ void bn_stats_kernel(const float* __restrict__ g,
                                const float* __restrict__ b) {
    const float* in = (STAGE == 0) ? g_buf1 : (STAGE == 1) ? g_buf3
                    : (STAGE == 2) ? g_buf5 : g_buf7;
    const int S = (STAGE == 0) ? S1 : (STAGE == 1) ? S2 : S3;
    int ch  = blockIdx.x;
    int grp = blockIdx.y;
    int n0 = grp ? NQIMG : 0;
    int n1 = grp ? NIMG : NQIMG;
    int SS = S * S;
    long total = (long)(n1 - n0) * SS;
    double sum = 0.0, sumsq = 0.0;
    for (long i = threadIdx.x; i < total; i += blockDim.x) {
        int n = n0 + (int)(i / SS);
        int p = (int)(i % SS);
        float v = in[((size_t)n * DCH + ch) * SS + p];
        sum += v;
        sumsq += (double)v * v;
    }
    __shared__ double s1[256], s2[256];
    int tid = threadIdx.x;
    s1[tid] = sum; s2[tid] = sumsq;
    __syncthreads();
    for (int off = 128; off > 0; off >>= 1) {
        if (tid < off) { s1[tid] += s1[tid + off]; s2[tid] += s2[tid + off]; }
        __syncthreads();
    }
    if (tid == 0) {
        double cnt = (double)total;
        double m   = s1[0] / cnt;
        double var = s2[0] / cnt - m * m;
        double inv = 1.0 / sqrt(var + 1e-5);
        float a = g[ch] * (float)inv;
        g_bnA[grp * DCH + ch] = a;
        g_bnC[grp * DCH + ch] = b[ch] - (float)(m) * a;
    }
}

// ---------------------------------------------------------------------------
// BN + LeakyReLU + 2x2 maxpool.  STAGE: 0 buf1(84)->buf2(42), 1 buf3(42)->buf4(21)
// ---------------------------------------------------------------------------
template <int STAGE>
__global__ void bn_pool_kernel() {
    const float* in = (STAGE == 0) ? g_buf1 : g_buf3;
    float*      out = (STAGE == 0) ? g_buf2 : g_buf4;
    const int S  = (STAGE == 0) ? S1 : S2;
    const int So = S / 2;
    long total = (long)NIMG * DCH * So * So;
    long idx = (long)blockIdx.x * blockDim.x + threadIdx.x;
    if (idx >= total) return;
    int SoSo = So * So;
    int p  = (int)(idx % SoSo);
    long t = idx / SoSo;
    int ch = (int)(t % DCH);
    int n  = (int)(t / DCH);
    int grp = (n < NQIMG) ? 0 : 1;
    float a = g_bnA[grp * DCH + ch];
    float c = g_bnC[grp * DCH + ch];
    int yo = p / So, xo = p % So;
    const float* base = in + ((size_t)n * DCH + ch) * S * S;
    float m = -1e30f;
#pragma unroll
    for (int dy = 0; dy < 2; dy++)
#pragma unroll
        for (int dx = 0; dx < 2; dx++) {
            float v = base[(2 * yo + dy) * S + (2 * xo + dx)] * a + c;
            v = (v > 0.f) ? v : LRELU_SLOPE * v;
            m = fmaxf(m, v);
        }
    out[idx] = m;
}

// ---------------------------------------------------------------------------
// BN + LeakyReLU (no pool), S=21. STAGE: 0 buf5->buf6, 1 buf7->buf8
// ---------------------------------------------------------------------------
template <int STAGE>
__global__ void bn_act_kernel() {
    const float* in = (STAGE == 0) ? g_buf5 : g_buf7;
    float*      out = (STAGE == 0) ? g_buf6 : g_buf8;
    long total = (long)NIMG * DCH * HW3;
    long idx = (long)blockIdx.x * blockDim.x + threadIdx.x;
    if (idx >= total) return;
    long t = idx / HW3;
    int ch = (int)(t % DCH);
    int n  = (int)(t / DCH);
    int grp = (n < NQIMG) ? 0 : 1;
    float v = in[idx] * g_bnA[grp * DCH + ch] + g_bnC[grp * DCH + ch];
    out[idx] = (v > 0.f) ? v : LRELU_SLOPE * v;
}

// ---------------------------------------------------------------------------
// L2-normalize per (image, spatial position) over 64 channels; scatter into
// descriptor layouts. One warp per position, lane covers channels d, d+32.
// ---------------------------------------------------------------------------
__global__ void normalize_kernel() {
    int warp = threadIdx.x >> 5;
    int lane = threadIdx.x & 31;
    int n = blockIdx.x;
    int l = blockIdx.y * 4 + warp;
    if (l >= HW3) return;
    const float* f = g_buf8 + (size_t)n * DCH * HW3;
    float x0 = f[lane * HW3 + l];
    float x1 = f[(lane + 32) * HW3 + l];
    float ss = x0 * x0 + x1 * x1;
#pragma unroll
    for (int off = 16; off > 0; off >>= 1)
        ss += __shfl_xor_sync(0xffffffffu, ss, off);
    float nrm = sqrtf(ss);
    float inv = 1.f / fmaxf(nrm, 1e-12f);
    float* dst;
    if (n < NQIMG) {
        dst = g_qdesc + ((size_t)n * HW3 + l) * DCH;
    } else {
        int sn = n - NQIMG;
        int b  = sn / 25;
        int w  = (sn % 25) / 5;
        int sh = sn % 5;
        dst = g_sdesc + (((size_t)(b * 5 + w) * MDIM) + sh * HW3 + l) * DCH;
    }
    dst[lane]      = x0 * inv;
    dst[lane + 32] = x1 * inv;
}

// ---------------------------------------------------------------------------
// Similarity + top-3 + sum. grid (150, 3): (b,q,w) x row-chunk of 147 rows.
// Thread = one q row (64-float vector in regs); s vectors tiled via smem.
// ---------------------------------------------------------------------------
__global__ void zero_out_kernel(float* out) {
    if (threadIdx.x < 150) out[threadIdx.x] = 0.f;
}

__global__ void sim_kernel(float* __restrict__ out) {
    int bqw = blockIdx.x;          // 0..149
    int bq  = bqw / 5;             // image (b*15+q)
    int w   = bqw % 5;
    int b   = bq / 15;
    int sw  = b * 5 + w;
    int l   = blockIdx.y * 147 + threadIdx.x;
    bool active = (threadIdx.x < 147);

    float4 qv[16];
    if (active) {
        const float4* qp = (const float4*)(g_qdesc + ((size_t)bq * HW3 + l) * DCH);
#pragma unroll
        for (int c = 0; c < 16; c++) qv[c] = qp[c];
    }

    float t0 = -1e30f, t1 = -1e30f, t2 = -1e30f;
    __shared__ float4 ssm[32 * 16];
    __shared__ float stotal;
    const float4* sp = (const float4*)(g_sdesc + (size_t)sw * MDIM * DCH);

    for (int m0 = 0; m0 < MDIM; m0 += 32) {
        int jmax = min(32, MDIM - m0);
        __syncthreads();
        for (int i = threadIdx.x; i < jmax * 16; i += 160)
            ssm[i] = sp[m0 * 16 + i];
        __syncthreads();
        if (active) {
            for (int j = 0; j < jmax; j++) {
                float acc = 0.f;
#pragma unroll
                for (int c = 0; c < 16; c++) {
                    float4 s = ssm[j * 16 + c];
                    float4 q = qv[c];
                    acc += s.x * q.x + s.y * q.y + s.z * q.z + s.w * q.w;
                }
                if (acc > t2) {
                    if (acc > t0)      { t2 = t1; t1 = t0; t0 = acc; }
                    else if (acc > t1) { t2 = t1; t1 = acc; }
                    else               { t2 = acc; }
                }
            }
        }
    }
    float v = active ? (t0 + t1 + t2) : 0.f;
#pragma unroll
    for (int off = 16; off > 0; off >>= 1)
        v += __shfl_down_sync(0xffffffffu, v, off);
    if (threadIdx.x == 0) stotal = 0.f;
    __syncthreads();
    if ((threadIdx.x & 31) == 0) atomicAdd(&stotal, v);
    __syncthreads();
    if (threadIdx.x == 0) atomicAdd(&out[bq * 5 + w], stotal);
}

// ---------------------------------------------------------------------------
// Launcher
// ---------------------------------------------------------------------------
extern "C" void kernel_launch(void* const* d_in, const int* in_sizes, int n_in,
                              void* d_out, int out_size) {
    const float* query   = (const float*)d_in[0];
    const float* support = (const float*)d_in[1];
    const float* W1 = (const float*)d_in[2];
    const float* W2 = (const float*)d_in[3];
    const float* W3 = (const float*)d_in[4];
    const float* W4 = (const float*)d_in[5];
    const float* g1 = (const float*)d_in[6];
    const float* b1 = (const float*)d_in[7];
    const float* g2 = (const float*)d_in[8];
    const float* b2 = (const float*)d_in[9];
    const float* g3 = (const float*)d_in[10];
    const float* b3 = (const float*)d_in[11];
    const float* g4 = (const float*)d_in[12];
    const float* b4 = (const float*)d_in[13];
    float* out = (float*)d_out;

    // layer 1: conv 3->64 @84, bn, lrelu, pool -> 42
    conv1_kernel<<<dim3(28, 64, 80), 256>>>(query, support, W1);
    bn_stats_kernel<0><<<dim3(64, 2), 256>>>(g1, b1);
    {
        long total = (long)NIMG * DCH * S2 * S2;
        bn_pool_kernel<0><<<(int)((total + 255) / 256), 256>>>();
    }
    // layer 2: conv 64->64 @42, bn, lrelu, pool -> 21
    conv64_kernel<S2, 0><<<dim3(16, 80), 256>>>(W2);
    bn_stats_kernel<1><<<dim3(64, 2), 256>>>(g2, b2);
    {
        long total = (long)NIMG * DCH * S3 * S3;
        bn_pool_kernel<1><<<(int)((total + 255) / 256), 256>>>();
    }
    // layer 3: conv 64->64 @21, bn, lrelu
    conv64_kernel<S3, 1><<<dim3(16, 80), 256>>>(W3);
    bn_stats_kernel<2><<<dim3(64, 2), 256>>>(g3, b3);
    {
        long total = (long)NIMG * DCH * HW3;
        bn_act_kernel<0><<<(int)((total + 255) / 256), 256>>>();
    }
    // layer 4: conv 64->64 @21, bn, lrelu
    conv64_kernel<S3, 2><<<dim3(16, 80), 256>>>(W4);
    bn_stats_kernel<3><<<dim3(64, 2), 256>>>(g4, b4);
    {
        long total = (long)NIMG * DCH * HW3;
        bn_act_kernel<1><<<(int)((total + 255) / 256), 256>>>();
    }
    // normalize into descriptor layouts
    normalize_kernel<<<dim3(80, 111), 128>>>();
    // similarity + top-3 + reduce
    zero_out_kernel<<<1, 160>>>(out);
    sim_kernel<<<dim3(150, 3), 160>>>(out);
}

// round 2
// speedup vs baseline: 1.3499x; 1.3499x over previous
#include <cuda_runtime.h>
#include <math.h>

// ---------------------------------------------------------------------------
// DN4Fast: Conv64F encoder (4x conv-bn-lrelu, 2x maxpool) on 80 images,
// L2-normalized local descriptors, cosine-sim top-3 scores.
// ---------------------------------------------------------------------------

#define NIMG   80
#define NQIMG  30
#define S1     84
#define S2     42
#define S3     21
#define DCH    64
#define HW3    (S3*S3)      // 441
#define MDIM   (5*HW3)      // 2205
#define LRELU_SLOPE 0.2f

__device__ float g_buf1[(size_t)NIMG*DCH*S1*S1];
__device__ float g_buf2[(size_t)NIMG*DCH*S2*S2];
__device__ float g_buf3[(size_t)NIMG*DCH*S2*S2];
__device__ float g_buf4[(size_t)NIMG*DCH*S3*S3];
__device__ float g_buf5[(size_t)NIMG*DCH*S3*S3];
__device__ float g_buf6[(size_t)NIMG*DCH*S3*S3];
__device__ float g_buf7[(size_t)NIMG*DCH*S3*S3];
__device__ float g_buf8[(size_t)NIMG*DCH*S3*S3];
__device__ float g_qdesc[(size_t)NQIMG*HW3*DCH];
__device__ float g_sdesc[(size_t)10*MDIM*DCH];
__device__ float g_bnA[2*DCH];
__device__ float g_bnC[2*DCH];

// ---------------------------------------------------------------------------
// conv1: 3 -> 64, 84x84 SAME. Block = (row-tile of 21, image). 256 threads.
// Image tile staged in smem; each thread: 1x7 strip x 8 output channels,
// looping over 8 channel-chunks.
// ---------------------------------------------------------------------------
__global__ __launch_bounds__(256)
void conv1_kernel(const float* __restrict__ q,
                  const float* __restrict__ s,
                  const float* __restrict__ W1) {
    __shared__ float img[3 * 23 * 86];
    __shared__ float wsm[64 * 27];
    int tid = threadIdx.x, n = blockIdx.y, ty = blockIdx.x;
    const float* src = (n < NQIMG) ? q + (size_t)n * 3 * S1 * S1
                                   : s + (size_t)(n - NQIMG) * 3 * S1 * S1;
    for (int i = tid; i < 64 * 27; i += 256) wsm[i] = W1[i];
    for (int i = tid; i < 3 * 23 * 86; i += 256) {
        int ci = i / (23 * 86);
        int r  = (i / 86) % 23;
        int c  = i % 86;
        int gy = ty * 21 + r - 1, gx = c - 1;
        img[i] = ((unsigned)gy < S1 && (unsigned)gx < S1)
                     ? src[ci * S1 * S1 + gy * S1 + gx] : 0.f;
    }
    __syncthreads();
    if (tid >= 252) return;
    int yl = tid / 12, x0 = (tid % 12) * 7;
    int gy = ty * 21 + yl;

    for (int cb = 0; cb < 8; cb++) {
        float acc[8][7];
#pragma unroll
        for (int c = 0; c < 8; c++)
#pragma unroll
            for (int px = 0; px < 7; px++) acc[c][px] = 0.f;
#pragma unroll
        for (int ci = 0; ci < 3; ci++) {
            float inr[27];
#pragma unroll
            for (int r = 0; r < 3; r++)
#pragma unroll
                for (int c = 0; c < 9; c++)
                    inr[r * 9 + c] = img[ci * 23 * 86 + (yl + r) * 86 + x0 + c];
#pragma unroll
            for (int k = 0; k < 9; k++) {
                int dy = k / 3, dx = k % 3;
                float wk[8];
#pragma unroll
                for (int c = 0; c < 8; c++)
                    wk[c] = wsm[(cb * 8 + c) * 27 + ci * 9 + k];
#pragma unroll
                for (int c = 0; c < 8; c++)
#pragma unroll
                    for (int px = 0; px < 7; px++)
                        acc[c][px] += inr[dy * 9 + px + dx] * wk[c];
            }
        }
#pragma unroll
        for (int c = 0; c < 8; c++) {
            int co = cb * 8 + c;
            float* op = g_buf1 + ((size_t)n * DCH + co) * (S1 * S1) + gy * S1 + x0;
#pragma unroll
            for (int px = 0; px < 7; px++) op[px] = acc[c][px];
        }
    }
}

// ---------------------------------------------------------------------------
// conv 64->64, SxS SAME. Register-blocked: thread = 1x7 strip x 8 co.
// CGPB co-groups of 8 per block. STAGE: 0 buf2->buf3, 1 buf4->buf5, 2 buf6->buf7
// ---------------------------------------------------------------------------
template <int S, int CGPB, int STAGE>
__global__ __launch_bounds__(256)
void conv64_kernel(const float* __restrict__ W) {
    constexpr int SP = S + 2;
    constexpr int SS = S * S;
    constexpr int STRIPS = S / 7;
    constexpr int NPOS = STRIPS * S;
    constexpr int NACT = NPOS * CGPB;
    constexpr int NT = ((NACT + 31) / 32) * 32;
    constexpr int NW = CGPB * 8 * 64 * 9;
    const float* in = (STAGE == 0) ? g_buf2 : (STAGE == 1) ? g_buf4 : g_buf6;
    float*      out = (STAGE == 0) ? g_buf3 : (STAGE == 1) ? g_buf5 : g_buf7;

    __shared__ float plane[SP * SP];
    __shared__ float wsm[NW];

    int tid = threadIdx.x;
    int n = blockIdx.y;
    int cobase_blk = blockIdx.x * CGPB * 8;

    for (int i = tid; i < NW; i += NT) wsm[i] = W[cobase_blk * 576 + i];

    int cg = tid / NPOS;
    int pos = tid % NPOS;
    bool active = tid < NACT;
    int y = pos / STRIPS, x0 = (pos % STRIPS) * 7;
    int cbase = cg * 8;

    float acc[8][7];
#pragma unroll
    for (int c = 0; c < 8; c++)
#pragma unroll
        for (int px = 0; px < 7; px++) acc[c][px] = 0.f;

    const float* ibase = in + (size_t)n * DCH * SS;

    for (int ci = 0; ci < DCH; ci++) {
        __syncthreads();
        for (int i = tid; i < SP * SP; i += NT) {
            int yy = i / SP - 1, xx = i % SP - 1;
            plane[i] = ((unsigned)yy < S && (unsigned)xx < S)
                           ? ibase[ci * SS + yy * S + xx] : 0.f;
        }
        __syncthreads();
        if (active) {
            float inr[27];
#pragma unroll
            for (int r = 0; r < 3; r++)
#pragma unroll
                for (int c = 0; c < 9; c++)
                    inr[r * 9 + c] = plane[(y + r) * SP + x0 + c];
#pragma unroll
            for (int k = 0; k < 9; k++) {
                int dy = k / 3, dx = k % 3;
                float wk[8];
#pragma unroll
                for (int c = 0; c < 8; c++)
                    wk[c] = wsm[((cbase + c) * 64 + ci) * 9 + k];
#pragma unroll
                for (int c = 0; c < 8; c++)
#pragma unroll
                    for (int px = 0; px < 7; px++)
                        acc[c][px] += inr[dy * 9 + px + dx] * wk[c];
            }
        }
    }
    if (active) {
#pragma unroll
        for (int c = 0; c < 8; c++) {
            int co = cobase_blk + cbase + c;
            float* op = out + ((size_t)n * DCH + co) * SS + y * S + x0;
#pragma unroll
            for (int px = 0; px < 7; px++) op[px] = acc[c][px];
        }
    }
}

// ---------------------------------------------------------------------------
// BN statistics per (group, channel). group 0 = imgs [0,30), 1 = [30,80).
// ---------------------------------------------------------------------------
template <int STAGE>
__global__ void bn_stats_kernel(const float* __restrict__ g,
                                const float* __restrict__ b) {
    const float* in = (STAGE == 0) ? g_buf1 : (STAGE == 1) ? g_buf3
                    : (STAGE == 2) ? g_buf5 : g_buf7;
    const int S = (STAGE == 0) ? S1 : (STAGE == 1) ? S2 : S3;
    int ch  = blockIdx.x;
    int grp = blockIdx.y;
    int n0 = grp ? NQIMG : 0;
    int n1 = grp ? NIMG : NQIMG;
    int SS = S * S;
    long total = (long)(n1 - n0) * SS;
    double sum = 0.0, sumsq = 0.0;
    for (long i = threadIdx.x; i < total; i += blockDim.x) {
        int n = n0 + (int)(i / SS);
        int p = (int)(i % SS);
        float v = in[((size_t)n * DCH + ch) * SS + p];
        sum += v;
        sumsq += (double)v * v;
    }
    __shared__ double s1[256], s2[256];
    int tid = threadIdx.x;
    s1[tid] = sum; s2[tid] = sumsq;
    __syncthreads();
    for (int off = 128; off > 0; off >>= 1) {
        if (tid < off) { s1[tid] += s1[tid + off]; s2[tid] += s2[tid + off]; }
        __syncthreads();
    }
    if (tid == 0) {
        double cnt = (double)total;
        double m   = s1[0] / cnt;
        double var = s2[0] / cnt - m * m;
        double inv = 1.0 / sqrt(var + 1e-5);
        float a = g[ch] * (float)inv;
        g_bnA[grp * DCH + ch] = a;
        g_bnC[grp * DCH + ch] = b[ch] - (float)(m) * a;
    }
}

// ---------------------------------------------------------------------------
// BN + LeakyReLU + 2x2 maxpool.
// ---------------------------------------------------------------------------
template <int STAGE>
__global__ void bn_pool_kernel() {
    const float* in = (STAGE == 0) ? g_buf1 : g_buf3;
    float*      out = (STAGE == 0) ? g_buf2 : g_buf4;
    const int S  = (STAGE == 0) ? S1 : S2;
    const int So = S / 2;
    long total = (long)NIMG * DCH * So * So;
    long idx = (long)blockIdx.x * blockDim.x + threadIdx.x;
    if (idx >= total) return;
    int SoSo = So * So;
    int p  = (int)(idx % SoSo);
    long t = idx / SoSo;
    int ch = (int)(t % DCH);
    int n  = (int)(t / DCH);
    int grp = (n < NQIMG) ? 0 : 1;
    float a = g_bnA[grp * DCH + ch];
    float c = g_bnC[grp * DCH + ch];
    int yo = p / So, xo = p % So;
    const float* base = in + ((size_t)n * DCH + ch) * S * S;
    float m = -1e30f;
#pragma unroll
    for (int dy = 0; dy < 2; dy++)
#pragma unroll
        for (int dx = 0; dx < 2; dx++) {
            float v = base[(2 * yo + dy) * S + (2 * xo + dx)] * a + c;
            v = (v > 0.f) ? v : LRELU_SLOPE * v;
            m = fmaxf(m, v);
        }
    out[idx] = m;
}

// ---------------------------------------------------------------------------
// BN + LeakyReLU (no pool), S=21.
// ---------------------------------------------------------------------------
template <int STAGE>
__global__ void bn_act_kernel() {
    const float* in = (STAGE == 0) ? g_buf5 : g_buf7;
    float*      out = (STAGE == 0) ? g_buf6 : g_buf8;
    long total = (long)NIMG * DCH * HW3;
    long idx = (long)blockIdx.x * blockDim.x + threadIdx.x;
    if (idx >= total) return;
    long t = idx / HW3;
    int ch = (int)(t % DCH);
    int n  = (int)(t / DCH);
    int grp = (n < NQIMG) ? 0 : 1;
    float v = in[idx] * g_bnA[grp * DCH + ch] + g_bnC[grp * DCH + ch];
    out[idx] = (v > 0.f) ? v : LRELU_SLOPE * v;
}

// ---------------------------------------------------------------------------
// L2-normalize + scatter to descriptor layouts.
// ---------------------------------------------------------------------------
__global__ void normalize_kernel() {
    int warp = threadIdx.x >> 5;
    int lane = threadIdx.x & 31;
    int n = blockIdx.x;
    int l = blockIdx.y * 4 + warp;
    if (l >= HW3) return;
    const float* f = g_buf8 + (size_t)n * DCH * HW3;
    float x0 = f[lane * HW3 + l];
    float x1 = f[(lane + 32) * HW3 + l];
    float ss = x0 * x0 + x1 * x1;
#pragma unroll
    for (int off = 16; off > 0; off >>= 1)
        ss += __shfl_xor_sync(0xffffffffu, ss, off);
    float nrm = sqrtf(ss);
    float inv = 1.f / fmaxf(nrm, 1e-12f);
    float* dst;
    if (n < NQIMG) {
        dst = g_qdesc + ((size_t)n * HW3 + l) * DCH;
    } else {
        int sn = n - NQIMG;
        int b  = sn / 25;
        int w  = (sn % 25) / 5;
        int sh = sn % 5;
        dst = g_sdesc + (((size_t)(b * 5 + w) * MDIM) + sh * HW3 + l) * DCH;
    }
    dst[lane]      = x0 * inv;
    dst[lane + 32] = x1 * inv;
}

// ---------------------------------------------------------------------------
// Similarity + top-3 + sum.
// ---------------------------------------------------------------------------
__global__ void zero_out_kernel(float* out) {
    if (threadIdx.x < 150) out[threadIdx.x] = 0.f;
}

__global__ void sim_kernel(float* __restrict__ out) {
    int bqw = blockIdx.x;
    int bq  = bqw / 5;
    int w   = bqw % 5;
    int b   = bq / 15;
    int sw  = b * 5 + w;
    int l   = blockIdx.y * 147 + threadIdx.x;
    bool active = (threadIdx.x < 147);

    float4 qv[16];
    if (active) {
        const float4* qp = (const float4*)(g_qdesc + ((size_t)bq * HW3 + l) * DCH);
#pragma unroll
        for (int c = 0; c < 16; c++) qv[c] = qp[c];
    }

    float t0 = -1e30f, t1 = -1e30f, t2 = -1e30f;
    __shared__ float4 ssm[32 * 16];
    __shared__ float stotal;
    const float4* sp = (const float4*)(g_sdesc + (size_t)sw * MDIM * DCH);

    for (int m0 = 0; m0 < MDIM; m0 += 32) {
        int jmax = min(32, MDIM - m0);
        __syncthreads();
        for (int i = threadIdx.x; i < jmax * 16; i += 160)
            ssm[i] = sp[m0 * 16 + i];
        __syncthreads();
        if (active) {
            for (int j = 0; j < jmax; j++) {
                float acc = 0.f;
#pragma unroll
                for (int c = 0; c < 16; c++) {
                    float4 s = ssm[j * 16 + c];
                    float4 q = qv[c];
                    acc += s.x * q.x + s.y * q.y + s.z * q.z + s.w * q.w;
                }
                if (acc > t2) {
                    if (acc > t0)      { t2 = t1; t1 = t0; t0 = acc; }
                    else if (acc > t1) { t2 = t1; t1 = acc; }
                    else               { t2 = acc; }
                }
            }
        }
    }
    float v = active ? (t0 + t1 + t2) : 0.f;
#pragma unroll
    for (int off = 16; off > 0; off >>= 1)
        v += __shfl_down_sync(0xffffffffu, v, off);
    if (threadIdx.x == 0) stotal = 0.f;
    __syncthreads();
    if ((threadIdx.x & 31) == 0) atomicAdd(&stotal, v);
    __syncthreads();
    if (threadIdx.x == 0) atomicAdd(&out[bq * 5 + w], stotal);
}

// ---------------------------------------------------------------------------
// Launcher
// ---------------------------------------------------------------------------
extern "C" void kernel_launch(void* const* d_in, const int* in_sizes, int n_in,
                              void* d_out, int out_size) {
    const float* query   = (const float*)d_in[0];
    const float* support = (const float*)d_in[1];
    const float* W1 = (const float*)d_in[2];
    const float* W2 = (const float*)d_in[3];
    const float* W3 = (const float*)d_in[4];
    const float* W4 = (const float*)d_in[5];
    const float* g1 = (const float*)d_in[6];
    const float* b1 = (const float*)d_in[7];
    const float* g2 = (const float*)d_in[8];
    const float* b2 = (const float*)d_in[9];
    const float* g3 = (const float*)d_in[10];
    const float* b3 = (const float*)d_in[11];
    const float* g4 = (const float*)d_in[12];
    const float* b4 = (const float*)d_in[13];
    float* out = (float*)d_out;

    // layer 1: conv 3->64 @84, bn, lrelu, pool -> 42
    conv1_kernel<<<dim3(4, 80), 256>>>(query, support, W1);
    bn_stats_kernel<0><<<dim3(64, 2), 256>>>(g1, b1);
    {
        long total = (long)NIMG * DCH * S2 * S2;
        bn_pool_kernel<0><<<(int)((total + 255) / 256), 256>>>();
    }
    // layer 2: conv 64->64 @42, bn, lrelu, pool -> 21
    conv64_kernel<S2, 1, 0><<<dim3(8, 80), 256>>>(W2);
    bn_stats_kernel<1><<<dim3(64, 2), 256>>>(g2, b2);
    {
        long total = (long)NIMG * DCH * S3 * S3;
        bn_pool_kernel<1><<<(int)((total + 255) / 256), 256>>>();
    }
    // layer 3: conv 64->64 @21, bn, lrelu
    conv64_kernel<S3, 2, 1><<<dim3(4, 80), 128>>>(W3);
    bn_stats_kernel<2><<<dim3(64, 2), 256>>>(g3, b3);
    {
        long total = (long)NIMG * DCH * HW3;
        bn_act_kernel<0><<<(int)((total + 255) / 256), 256>>>();
    }
    // layer 4: conv 64->64 @21, bn, lrelu
    conv64_kernel<S3, 2, 2><<<dim3(4, 80), 128>>>(W4);
    bn_stats_kernel<3><<<dim3(64, 2), 256>>>(g4, b4);
    {
        long total = (long)NIMG * DCH * HW3;
        bn_act_kernel<1><<<(int)((total + 255) / 256), 256>>>();
    }
    // normalize into descriptor layouts
    normalize_kernel<<<dim3(80, 111), 128>>>();
    // similarity + top-3 + reduce
    zero_out_kernel<<<1, 160>>>(out);
    sim_kernel<<<dim3(150, 3), 160>>>(out);
}

// round 4
// speedup vs baseline: 1.5386x; 1.1398x over previous
#include <cuda_runtime.h>
#include <math.h>

#define NIMG   80
#define NQIMG  30
#define S1     84
#define S2     42
#define S3     21
#define DCH    64
#define HW3    (S3*S3)      // 441
#define MDIM   (5*HW3)      // 2205
#define NPAIR  1102         // full row-pairs in M
#define NPROWS 1103         // pair slots allocated (incl. tail)
#define LRELU_SLOPE 0.2f

typedef unsigned long long ull;

__device__ float g_buf1[(size_t)NIMG*DCH*S1*S1];
__device__ float g_buf2[(size_t)NIMG*DCH*S2*S2];
__device__ float g_buf3[(size_t)NIMG*DCH*S2*S2];
__device__ float g_buf4[(size_t)NIMG*DCH*S3*S3];
__device__ float g_buf5[(size_t)NIMG*DCH*S3*S3];
__device__ float g_buf6[(size_t)NIMG*DCH*S3*S3];
__device__ float g_buf7[(size_t)NIMG*DCH*S3*S3];
__device__ float g_buf8[(size_t)NIMG*DCH*S3*S3];
__device__ float g_qdesc[(size_t)NQIMG*HW3*DCH];
// pair-interleaved: [sw][mp][c][parity], mp in [0,1103), c in [0,64)
__device__ float g_sdesc2[(size_t)10*NPROWS*DCH*2];
__device__ float g_bnA[2*DCH];
__device__ float g_bnC[2*DCH];

// ---------------- f32x2 helpers ----------------
__device__ __forceinline__ ull dup2(float x) {
    ull r; asm("mov.b64 %0, {%1, %2};" : "=l"(r) : "f"(x), "f"(x)); return r;
}
__device__ __forceinline__ ull pack2(float lo, float hi) {
    ull r; asm("mov.b64 %0, {%1, %2};" : "=l"(r) : "f"(lo), "f"(hi)); return r;
}
__device__ __forceinline__ ull ffma2(ull a, ull b, ull c) {
    ull d; asm("fma.rn.f32x2 %0, %1, %2, %3;" : "=l"(d) : "l"(a), "l"(b), "l"(c)); return d;
}
__device__ __forceinline__ ull addf2(ull a, ull b) {
    ull d; asm("add.rn.f32x2 %0, %1, %2;" : "=l"(d) : "l"(a), "l"(b)); return d;
}
__device__ __forceinline__ float2 unpack2(ull v) {
    float2 f; asm("mov.b64 {%0, %1}, %2;" : "=f"(f.x), "=f"(f.y) : "l"(v)); return f;
}

// ---------------------------------------------------------------------------
// conv1: 3 -> 64, 84x84 SAME.
// ---------------------------------------------------------------------------
__global__ __launch_bounds__(256)
void conv1_kernel(const float* __restrict__ q,
                  const float* __restrict__ s,
                  const float* __restrict__ W1) {
    __shared__ float img[3 * 23 * 86];
    __shared__ float wsm[64 * 27];
    int tid = threadIdx.x, n = blockIdx.y, ty = blockIdx.x;
    const float* src = (n < NQIMG) ? q + (size_t)n * 3 * S1 * S1
                                   : s + (size_t)(n - NQIMG) * 3 * S1 * S1;
    for (int i = tid; i < 64 * 27; i += 256) wsm[i] = W1[i];
    for (int i = tid; i < 3 * 23 * 86; i += 256) {
        int ci = i / (23 * 86);
        int r  = (i / 86) % 23;
        int c  = i % 86;
        int gy = ty * 21 + r - 1, gx = c - 1;
        img[i] = ((unsigned)gy < S1 && (unsigned)gx < S1)
                     ? src[ci * S1 * S1 + gy * S1 + gx] : 0.f;
    }
    __syncthreads();
    if (tid >= 252) return;
    int yl = tid / 12, x0 = (tid % 12) * 7;
    int gy = ty * 21 + yl;

    for (int cb = 0; cb < 8; cb++) {
        float acc[8][7];
#pragma unroll
        for (int c = 0; c < 8; c++)
#pragma unroll
            for (int px = 0; px < 7; px++) acc[c][px] = 0.f;
#pragma unroll
        for (int ci = 0; ci < 3; ci++) {
            float inr[27];
#pragma unroll
            for (int r = 0; r < 3; r++)
#pragma unroll
                for (int c = 0; c < 9; c++)
                    inr[r * 9 + c] = img[ci * 23 * 86 + (yl + r) * 86 + x0 + c];
#pragma unroll
            for (int k = 0; k < 9; k++) {
                int dy = k / 3, dx = k % 3;
                float wk[8];
#pragma unroll
                for (int c = 0; c < 8; c++)
                    wk[c] = wsm[(cb * 8 + c) * 27 + ci * 9 + k];
#pragma unroll
                for (int c = 0; c < 8; c++)
#pragma unroll
                    for (int px = 0; px < 7; px++)
                        acc[c][px] += inr[dy * 9 + px + dx] * wk[c];
            }
        }
#pragma unroll
        for (int c = 0; c < 8; c++) {
            int co = cb * 8 + c;
            float* op = g_buf1 + ((size_t)n * DCH + co) * (S1 * S1) + gy * S1 + x0;
#pragma unroll
            for (int px = 0; px < 7; px++) op[px] = acc[c][px];
        }
    }
}

// ---------------------------------------------------------------------------
// conv 64->64 with packed f32x2 FMA.
// Block = 8 output channels (4 pairs) x one image. Thread = 1x7 strip.
// Input plane staged in smem as PLAIN floats (double-buffered); duplication
// to (x,x) pairs happens at register load (1 mov.b64 per element).
// Weights in smem pair-interleaved over output-channel pairs (LDS.64).
// STAGE: 0 buf2->buf3 (S=42), 1 buf4->buf5 (S=21), 2 buf6->buf7 (S=21)
// ---------------------------------------------------------------------------
template <int S, int STAGE>
__global__ __launch_bounds__(S == 42 ? 256 : 64)
void conv64f2_kernel(const float* __restrict__ W) {
    constexpr int SP = S + 2;
    constexpr int SPSP = SP * SP;
    constexpr int SS = S * S;
    constexpr int STRIPS = S / 7;
    constexpr int NPOS = STRIPS * S;
    constexpr int NT = (S == 42) ? 256 : 64;
    const float* in = (STAGE == 0) ? g_buf2 : (STAGE == 1) ? g_buf4 : g_buf6;
    float*      out = (STAGE == 0) ? g_buf3 : (STAGE == 1) ? g_buf5 : g_buf7;

    __shared__ float plane[2][SPSP];        // plain floats
    __shared__ ull wsm2[4 * 64 * 9];        // packed co-pairs

    int tid = threadIdx.x;
    int n = blockIdx.y;
    int cobase = blockIdx.x * 8;

    // weights: pair-interleaved (cp, ci, k) -> packed (w_{2cp}, w_{2cp+1})
    for (int i = tid; i < 4 * 64 * 9; i += NT) {
        int cp = i / (64 * 9);
        int rem = i % (64 * 9);
        int ci = rem / 9, k = rem % 9;
        float w0 = W[(cobase + cp * 2) * 576 + ci * 9 + k];
        float w1 = W[(cobase + cp * 2 + 1) * 576 + ci * 9 + k];
        wsm2[i] = pack2(w0, w1);
    }

    bool active = tid < NPOS;
    int y = tid / STRIPS, x0 = (tid % STRIPS) * 7;

    ull acc[4][7];
#pragma unroll
    for (int cp = 0; cp < 4; cp++)
#pragma unroll
        for (int px = 0; px < 7; px++) acc[cp][px] = 0ull;

    const float* ibase = in + (size_t)n * DCH * SS;

    // stage channel 0 into buffer 0
    {
        const float* src = ibase;
        for (int i = tid; i < SPSP; i += NT) {
            int yy = i / SP - 1, xx = i % SP - 1;
            plane[0][i] = ((unsigned)yy < S && (unsigned)xx < S)
                              ? src[yy * S + xx] : 0.f;
        }
    }

    for (int ci = 0; ci < DCH; ci++) {
        __syncthreads();   // plane[ci&1] ready; prior compute on other buffer done
        if (ci + 1 < DCH) {
            const float* src = ibase + (ci + 1) * SS;
            int bidx = (ci + 1) & 1;
            for (int i = tid; i < SPSP; i += NT) {
                int yy = i / SP - 1, xx = i % SP - 1;
                plane[bidx][i] = ((unsigned)yy < S && (unsigned)xx < S)
                                     ? src[yy * S + xx] : 0.f;
            }
        }
        if (active) {
            const float* pb = plane[ci & 1];
#pragma unroll
            for (int dy = 0; dy < 3; dy++) {
                ull inr2[9];
#pragma unroll
                for (int c = 0; c < 9; c++)
                    inr2[c] = dup2(pb[(y + dy) * SP + x0 + c]);
#pragma unroll
                for (int dx = 0; dx < 3; dx++) {
                    int k = dy * 3 + dx;
#pragma unroll
                    for (int cp = 0; cp < 4; cp++) {
                        ull wk = wsm2[(cp * 64 + ci) * 9 + k];
#pragma unroll
                        for (int px = 0; px < 7; px++)
                            acc[cp][px] = ffma2(inr2[px + dx], wk, acc[cp][px]);
                    }
                }
            }
        }
    }
    if (active) {
#pragma unroll
        for (int cp = 0; cp < 4; cp++) {
            float* o0 = out + ((size_t)n * DCH + cobase + 2 * cp) * SS + y * S + x0;
            float* o1 = o0 + SS;
#pragma unroll
            for (int px = 0; px < 7; px++) {
                float2 f = unpack2(acc[cp][px]);
                o0[px] = f.x;
                o1[px] = f.y;
            }
        }
    }
}

// ---------------------------------------------------------------------------
// BN statistics per (group, channel), fp32 accumulation.
// ---------------------------------------------------------------------------
template <int STAGE>
__global__ void bn_stats_kernel(const float* __restrict__ g,
                                const float* __restrict__ b) {
    const float* in = (STAGE == 0) ? g_buf1 : (STAGE == 1) ? g_buf3
                    : (STAGE == 2) ? g_buf5 : g_buf7;
    const int S = (STAGE == 0) ? S1 : (STAGE == 1) ? S2 : S3;
    int ch  = blockIdx.x;
    int grp = blockIdx.y;
    int n0 = grp ? NQIMG : 0;
    int n1 = grp ? NIMG : NQIMG;
    int SS = S * S;
    long total = (long)(n1 - n0) * SS;
    float sum = 0.f, sumsq = 0.f;
    for (long i = threadIdx.x; i < total; i += blockDim.x) {
        int n = n0 + (int)(i / SS);
        int p = (int)(i % SS);
        float v = in[((size_t)n * DCH + ch) * SS + p];
        sum += v;
        sumsq += v * v;
    }
    __shared__ float s1[256], s2[256];
    int tid = threadIdx.x;
    s1[tid] = sum; s2[tid] = sumsq;
    __syncthreads();
    for (int off = 128; off > 0; off >>= 1) {
        if (tid < off) { s1[tid] += s1[tid + off]; s2[tid] += s2[tid + off]; }
        __syncthreads();
    }
    if (tid == 0) {
        double cnt = (double)total;
        double m   = (double)s1[0] / cnt;
        double var = (double)s2[0] / cnt - m * m;
        double inv = 1.0 / sqrt(var + 1e-5);
        float a = g[ch] * (float)inv;
        g_bnA[grp * DCH + ch] = a;
        g_bnC[grp * DCH + ch] = b[ch] - (float)m * a;
    }
}

// ---------------------------------------------------------------------------
// BN + LeakyReLU + 2x2 maxpool.
// ---------------------------------------------------------------------------
template <int STAGE>
__global__ void bn_pool_kernel() {
    const float* in = (STAGE == 0) ? g_buf1 : g_buf3;
    float*      out = (STAGE == 0) ? g_buf2 : g_buf4;
    const int S  = (STAGE == 0) ? S1 : S2;
    const int So = S / 2;
    long total = (long)NIMG * DCH * So * So;
    long idx = (long)blockIdx.x * blockDim.x + threadIdx.x;
    if (idx >= total) return;
    int SoSo = So * So;
    int p  = (int)(idx % SoSo);
    long t = idx / SoSo;
    int ch = (int)(t % DCH);
    int n  = (int)(t / DCH);
    int grp = (n < NQIMG) ? 0 : 1;
    float a = g_bnA[grp * DCH + ch];
    float c = g_bnC[grp * DCH + ch];
    int yo = p / So, xo = p % So;
    const float* base = in + ((size_t)n * DCH + ch) * S * S;
    float m = -1e30f;
#pragma unroll
    for (int dy = 0; dy < 2; dy++)
#pragma unroll
        for (int dx = 0; dx < 2; dx++) {
            float v = base[(2 * yo + dy) * S + (2 * xo + dx)] * a + c;
            v = (v > 0.f) ? v : LRELU_SLOPE * v;
            m = fmaxf(m, v);
        }
    out[idx] = m;
}

// ---------------------------------------------------------------------------
// BN + LeakyReLU (no pool), S=21.
// ---------------------------------------------------------------------------
template <int STAGE>
__global__ void bn_act_kernel() {
    const float* in = (STAGE == 0) ? g_buf5 : g_buf7;
    float*      out = (STAGE == 0) ? g_buf6 : g_buf8;
    long total = (long)NIMG * DCH * HW3;
    long idx = (long)blockIdx.x * blockDim.x + threadIdx.x;
    if (idx >= total) return;
    long t = idx / HW3;
    int ch = (int)(t % DCH);
    int n  = (int)(t / DCH);
    int grp = (n < NQIMG) ? 0 : 1;
    float v = in[idx] * g_bnA[grp * DCH + ch] + g_bnC[grp * DCH + ch];
    out[idx] = (v > 0.f) ? v : LRELU_SLOPE * v;
}

// ---------------------------------------------------------------------------
// L2-normalize + scatter. q -> contiguous (bq, l, c); s -> pair-interleaved.
// ---------------------------------------------------------------------------
__global__ void normalize_kernel() {
    int warp = threadIdx.x >> 5;
    int lane = threadIdx.x & 31;
    int n = blockIdx.x;
    int l = blockIdx.y * 4 + warp;
    if (l >= HW3) return;
    const float* f = g_buf8 + (size_t)n * DCH * HW3;
    float x0 = f[lane * HW3 + l];
    float x1 = f[(lane + 32) * HW3 + l];
    float ss = x0 * x0 + x1 * x1;
#pragma unroll
    for (int off = 16; off > 0; off >>= 1)
        ss += __shfl_xor_sync(0xffffffffu, ss, off);
    float nrm = sqrtf(ss);
    float inv = 1.f / fmaxf(nrm, 1e-12f);
    if (n < NQIMG) {
        float* dst = g_qdesc + ((size_t)n * HW3 + l) * DCH;
        dst[lane]      = x0 * inv;
        dst[lane + 32] = x1 * inv;
    } else {
        int sn = n - NQIMG;
        int b  = sn / 25;
        int w  = (sn % 25) / 5;
        int sh = sn % 5;
        int sw = b * 5 + w;
        int m  = sh * HW3 + l;
        int mp = m >> 1, par = m & 1;
        float* base = g_sdesc2 + (size_t)sw * NPROWS * DCH * 2 + (size_t)mp * DCH * 2;
        base[lane * 2 + par]        = x0 * inv;
        base[(lane + 32) * 2 + par] = x1 * inv;
    }
}

// ---------------------------------------------------------------------------
// Similarity + top-3 + sum, packed f32x2. Thread = one q row (l).
// s rows processed two at a time via pair-interleaved layout.
// ---------------------------------------------------------------------------
__global__ void zero_out_kernel(float* out) {
    if (threadIdx.x < 150) out[threadIdx.x] = 0.f;
}

#define TOPK_UPDATE(val)                                        \
    do { float _v = (val);                                      \
        if (_v > t2) {                                          \
            if (_v > t0)      { t2 = t1; t1 = t0; t0 = _v; }    \
            else if (_v > t1) { t2 = t1; t1 = _v; }             \
            else              { t2 = _v; }                      \
        } } while (0)

__global__ __launch_bounds__(160)
void simf2_kernel(float* __restrict__ out) {
    int bqw = blockIdx.x;          // 0..149
    int bq  = bqw / 5;
    int w   = bqw % 5;
    int b   = bq / 15;
    int sw  = b * 5 + w;
    int l   = blockIdx.y * 147 + threadIdx.x;
    bool active = (threadIdx.x < 147);

    ull qd[64];
    if (active) {
        const float4* qp = (const float4*)(g_qdesc + ((size_t)bq * HW3 + l) * DCH);
#pragma unroll
        for (int c = 0; c < 16; c++) {
            float4 v = qp[c];
            qd[4 * c + 0] = dup2(v.x);
            qd[4 * c + 1] = dup2(v.y);
            qd[4 * c + 2] = dup2(v.z);
            qd[4 * c + 3] = dup2(v.w);
        }
    }

    float t0 = -1e30f, t1 = -1e30f, t2 = -1e30f;
    __shared__ ulonglong2 ssm[32 * 32];   // 32 row-pairs x 64 channels (packed)
    __shared__ float stotal;
    const ulonglong2* sp =
        (const ulonglong2*)(g_sdesc2 + (size_t)sw * NPROWS * DCH * 2);

    for (int mp0 = 0; mp0 < NPAIR; mp0 += 32) {
        int jmax = min(32, NPAIR - mp0);
        __syncthreads();
        for (int i = threadIdx.x; i < jmax * 32; i += 160)
            ssm[i] = sp[(size_t)mp0 * 32 + i];
        __syncthreads();
        if (active) {
            for (int j = 0; j < jmax; j++) {
                const ulonglong2* row = &ssm[j * 32];
                ull a0 = 0, a1 = 0, a2 = 0, a3 = 0;
#pragma unroll
                for (int u = 0; u < 32; u += 2) {
                    ulonglong2 v0 = row[u];
                    ulonglong2 v1 = row[u + 1];
                    a0 = ffma2(qd[2 * u + 0], v0.x, a0);
                    a1 = ffma2(qd[2 * u + 1], v0.y, a1);
                    a2 = ffma2(qd[2 * u + 2], v1.x, a2);
                    a3 = ffma2(qd[2 * u + 3], v1.y, a3);
                }
                float2 f = unpack2(addf2(addf2(a0, a1), addf2(a2, a3)));
                TOPK_UPDATE(f.x);
                TOPK_UPDATE(f.y);
            }
        }
    }
    // tail row m = 2204 (pair slot 1102, parity 0)
    if (active) {
        const float* srow = g_sdesc2 + (size_t)sw * NPROWS * DCH * 2
                          + (size_t)NPAIR * DCH * 2;
        float acc = 0.f;
#pragma unroll
        for (int c = 0; c < 64; c++) {
            float qc = unpack2(qd[c]).x;
            acc += qc * srow[c * 2];
        }
        TOPK_UPDATE(acc);
    }

    float v = active ? (t0 + t1 + t2) : 0.f;
#pragma unroll
    for (int off = 16; off > 0; off >>= 1)
        v += __shfl_down_sync(0xffffffffu, v, off);
    if (threadIdx.x == 0) stotal = 0.f;
    __syncthreads();
    if ((threadIdx.x & 31) == 0) atomicAdd(&stotal, v);
    __syncthreads();
    if (threadIdx.x == 0) atomicAdd(&out[bq * 5 + w], stotal);
}

// ---------------------------------------------------------------------------
// Launcher
// ---------------------------------------------------------------------------
extern "C" void kernel_launch(void* const* d_in, const int* in_sizes, int n_in,
                              void* d_out, int out_size) {
    const float* query   = (const float*)d_in[0];
    const float* support = (const float*)d_in[1];
    const float* W1 = (const float*)d_in[2];
    const float* W2 = (const float*)d_in[3];
    const float* W3 = (const float*)d_in[4];
    const float* W4 = (const float*)d_in[5];
    const float* g1 = (const float*)d_in[6];
    const float* b1 = (const float*)d_in[7];
    const float* g2 = (const float*)d_in[8];
    const float* b2 = (const float*)d_in[9];
    const float* g3 = (const float*)d_in[10];
    const float* b3 = (const float*)d_in[11];
    const float* g4 = (const float*)d_in[12];
    const float* b4 = (const float*)d_in[13];
    float* out = (float*)d_out;

    // layer 1
    conv1_kernel<<<dim3(4, 80), 256>>>(query, support, W1);
    bn_stats_kernel<0><<<dim3(64, 2), 256>>>(g1, b1);
    {
        long total = (long)NIMG * DCH * S2 * S2;
        bn_pool_kernel<0><<<(int)((total + 255) / 256), 256>>>();
    }
    // layer 2
    conv64f2_kernel<S2, 0><<<dim3(8, 80), 256>>>(W2);
    bn_stats_kernel<1><<<dim3(64, 2), 256>>>(g2, b2);
    {
        long total = (long)NIMG * DCH * S3 * S3;
        bn_pool_kernel<1><<<(int)((total + 255) / 256), 256>>>();
    }
    // layer 3
    conv64f2_kernel<S3, 1><<<dim3(8, 80), 64>>>(W3);
    bn_stats_kernel<2><<<dim3(64, 2), 256>>>(g3, b3);
    {
        long total = (long)NIMG * DCH * HW3;
        bn_act_kernel<0><<<(int)((total + 255) / 256), 256>>>();
    }
    // layer 4
    conv64f2_kernel<S3, 2><<<dim3(8, 80), 64>>>(W4);
    bn_stats_kernel<3><<<dim3(64, 2), 256>>>(g4, b4);
    {
        long total = (long)NIMG * DCH * HW3;
        bn_act_kernel<1><<<(int)((total + 255) / 256), 256>>>();
    }
    // normalize + scatter
    normalize_kernel<<<dim3(80, 111), 128>>>();
    // similarity
    zero_out_kernel<<<1, 160>>>(out);
    simf2_kernel<<<dim3(150, 3), 160>>>(out);
}

// round 6
// speedup vs baseline: 2.4808x; 1.6124x over previous
#include <cuda_runtime.h>
#include <cuda_bf16.h>
#include <stdint.h>
#include <math.h>

#define NIMG   80
#define NQIMG  30
#define S1     84
#define S2     42
#define S3     21
#define DCH    64
#define HW3    (S3*S3)      // 441
#define MDIM   (5*HW3)      // 2205
#define QPAD   512          // q rows padded (441 -> 512)
#define SPAD   2304         // s rows padded (2205 -> 2304 = 9*256)
#define LRELU_SLOPE 0.2f

typedef unsigned long long ull;
typedef unsigned int u32;

__device__ float g_buf1[(size_t)NIMG*DCH*S1*S1];
__device__ float g_buf2[(size_t)NIMG*DCH*S2*S2];
__device__ float g_buf3[(size_t)NIMG*DCH*S2*S2];   // conv2 partial ks=0
__device__ float g_buf3b[(size_t)NIMG*DCH*S2*S2];  // conv2 partial ks=1
__device__ float g_buf4[(size_t)NIMG*DCH*S3*S3];
__device__ float g_buf5[(size_t)NIMG*DCH*S3*S3];
__device__ float g_buf5b[(size_t)NIMG*DCH*S3*S3];
__device__ float g_buf6[(size_t)NIMG*DCH*S3*S3];
__device__ float g_buf7[(size_t)NIMG*DCH*S3*S3];
__device__ float g_buf7b[(size_t)NIMG*DCH*S3*S3];
__device__ float g_buf8[(size_t)NIMG*DCH*S3*S3];
// bf16 descriptors; padded rows stay 0 (BSS, never written) -> deterministic
__device__ __nv_bfloat16 g_qbf[(size_t)NQIMG*QPAD*DCH];
__device__ __nv_bfloat16 g_sbf[(size_t)10*SPAD*DCH];
__device__ float g_bnA[2*DCH];
__device__ float g_bnC[2*DCH];
__device__ float g_stat[4][2][DCH][2];   // [stage][grp][ch][{sum,sumsq}]

// ---------------- f32x2 helpers ----------------
__device__ __forceinline__ ull pack2(float lo, float hi) {
    ull r; asm("mov.b64 %0, {%1, %2};" : "=l"(r) : "f"(lo), "f"(hi)); return r;
}
__device__ __forceinline__ ull dup2(float x) {
    ull r; asm("mov.b64 %0, {%1, %2};" : "=l"(r) : "f"(x), "f"(x)); return r;
}
__device__ __forceinline__ ull ffma2(ull a, ull b, ull c) {
    ull d; asm("fma.rn.f32x2 %0, %1, %2, %3;" : "=l"(d) : "l"(a), "l"(b), "l"(c)); return d;
}
__device__ __forceinline__ float2 unpack2(ull v) {
    float2 f; asm("mov.b64 {%0, %1}, %2;" : "=f"(f.x), "=f"(f.y) : "l"(v)); return f;
}

#define TOPK3(t0, t1, t2, val)                                   \
    do { float _v = (val);                                       \
        if (_v > (t2)) {                                         \
            if (_v > (t0))      { (t2)=(t1); (t1)=(t0); (t0)=_v; } \
            else if (_v > (t1)) { (t2)=(t1); (t1)=_v; }          \
            else                { (t2)=_v; }                     \
        } } while (0)

// ---------------------------------------------------------------------------
// zero misc: stats accumulators + output
// ---------------------------------------------------------------------------
__global__ void zero_misc_kernel(float* out) {
    int tid = threadIdx.x;
    float* st = &g_stat[0][0][0][0];
    if (tid < 1024) st[tid] = 0.f;
    if (tid < 150)  out[tid] = 0.f;
}

// ---------------------------------------------------------------------------
// conv1: 3 -> 64, 84x84 SAME.
// ---------------------------------------------------------------------------
__global__ __launch_bounds__(256)
void conv1_kernel(const float* __restrict__ q,
                  const float* __restrict__ s,
                  const float* __restrict__ W1) {
    __shared__ float img[3 * 23 * 86];
    __shared__ float wsm[64 * 27];
    int tid = threadIdx.x, n = blockIdx.y, ty = blockIdx.x;
    const float* src = (n < NQIMG) ? q + (size_t)n * 3 * S1 * S1
                                   : s + (size_t)(n - NQIMG) * 3 * S1 * S1;
    for (int i = tid; i < 64 * 27; i += 256) wsm[i] = W1[i];
    for (int i = tid; i < 3 * 23 * 86; i += 256) {
        int ci = i / (23 * 86);
        int r  = (i / 86) % 23;
        int c  = i % 86;
        int gy = ty * 21 + r - 1, gx = c - 1;
        img[i] = ((unsigned)gy < S1 && (unsigned)gx < S1)
                     ? src[ci * S1 * S1 + gy * S1 + gx] : 0.f;
    }
    __syncthreads();
    if (tid >= 252) return;
    int yl = tid / 12, x0 = (tid % 12) * 7;
    int gy = ty * 21 + yl;

    for (int cb = 0; cb < 8; cb++) {
        float acc[8][7];
#pragma unroll
        for (int c = 0; c < 8; c++)
#pragma unroll
            for (int px = 0; px < 7; px++) acc[c][px] = 0.f;
#pragma unroll
        for (int ci = 0; ci < 3; ci++) {
            float inr[27];
#pragma unroll
            for (int r = 0; r < 3; r++)
#pragma unroll
                for (int c = 0; c < 9; c++)
                    inr[r * 9 + c] = img[ci * 23 * 86 + (yl + r) * 86 + x0 + c];
#pragma unroll
            for (int k = 0; k < 9; k++) {
                int dy = k / 3, dx = k % 3;
                float wk[8];
#pragma unroll
                for (int c = 0; c < 8; c++)
                    wk[c] = wsm[(cb * 8 + c) * 27 + ci * 9 + k];
#pragma unroll
                for (int c = 0; c < 8; c++)
#pragma unroll
                    for (int px = 0; px < 7; px++)
                        acc[c][px] += inr[dy * 9 + px + dx] * wk[c];
            }
        }
#pragma unroll
        for (int c = 0; c < 8; c++) {
            int co = cb * 8 + c;
            float* op = g_buf1 + ((size_t)n * DCH + co) * (S1 * S1) + gy * S1 + x0;
#pragma unroll
            for (int px = 0; px < 7; px++) op[px] = acc[c][px];
        }
    }
}

// ---------------------------------------------------------------------------
// conv 64->64, K-split in 2 halves (blockIdx.z). f32x2 packed over co-pairs.
// STAGE: 0 buf2 -> buf3/buf3b (S=42), 1 buf4 -> buf5/5b (S=21),
//        2 buf6 -> buf7/7b (S=21)
// ---------------------------------------------------------------------------
template <int S, int STAGE>
__global__ __launch_bounds__(S == 42 ? 256 : 64)
void conv64split_kernel(const float* __restrict__ W) {
    constexpr int SP = S + 2;
    constexpr int SPSP = SP * SP;
    constexpr int SS = S * S;
    constexpr int STRIPS = S / 7;
    constexpr int NPOS = STRIPS * S;
    constexpr int NT = (S == 42) ? 256 : 64;
    const float* in = (STAGE == 0) ? g_buf2 : (STAGE == 1) ? g_buf4 : g_buf6;
    float* outA = (STAGE == 0) ? g_buf3 : (STAGE == 1) ? g_buf5 : g_buf7;
    float* outB = (STAGE == 0) ? g_buf3b : (STAGE == 1) ? g_buf5b : g_buf7b;

    __shared__ float plane[2][SPSP];
    __shared__ ull wsm2[4 * 32 * 9];

    int tid = threadIdx.x;
    int n = blockIdx.y;
    int ks = blockIdx.z;
    int ci0 = ks * 32;
    int cobase = blockIdx.x * 8;
    float* out = ks ? outB : outA;

    // weights for this ci-half, pair-interleaved over co-pairs
    for (int i = tid; i < 4 * 32 * 9; i += NT) {
        int cp = i / 288;
        int rem = i % 288;
        int ic = rem / 9, k = rem % 9;
        float w0 = W[(cobase + cp * 2) * 576 + (ci0 + ic) * 9 + k];
        float w1 = W[(cobase + cp * 2 + 1) * 576 + (ci0 + ic) * 9 + k];
        wsm2[i] = pack2(w0, w1);
    }

    bool active = tid < NPOS;
    int y = tid / STRIPS, x0 = (tid % STRIPS) * 7;

    ull acc[4][7];
#pragma unroll
    for (int cp = 0; cp < 4; cp++)
#pragma unroll
        for (int px = 0; px < 7; px++) acc[cp][px] = 0ull;

    const float* ibase = in + (size_t)n * DCH * SS + (size_t)ci0 * SS;

    {   // stage first channel
        const float* src = ibase;
        for (int i = tid; i < SPSP; i += NT) {
            int yy = i / SP - 1, xx = i % SP - 1;
            plane[0][i] = ((unsigned)yy < S && (unsigned)xx < S)
                              ? src[yy * S + xx] : 0.f;
        }
    }

    for (int ic = 0; ic < 32; ic++) {
        __syncthreads();
        if (ic + 1 < 32) {
            const float* src = ibase + (ic + 1) * SS;
            int bidx = (ic + 1) & 1;
            for (int i = tid; i < SPSP; i += NT) {
                int yy = i / SP - 1, xx = i % SP - 1;
                plane[bidx][i] = ((unsigned)yy < S && (unsigned)xx < S)
                                     ? src[yy * S + xx] : 0.f;
            }
        }
        if (active) {
            const float* pb = plane[ic & 1];
#pragma unroll
            for (int dy = 0; dy < 3; dy++) {
                ull inr2[9];
#pragma unroll
                for (int c = 0; c < 9; c++)
                    inr2[c] = dup2(pb[(y + dy) * SP + x0 + c]);
#pragma unroll
                for (int dx = 0; dx < 3; dx++) {
                    int k = dy * 3 + dx;
#pragma unroll
                    for (int cp = 0; cp < 4; cp++) {
                        ull wk = wsm2[(cp * 32 + ic) * 9 + k];
#pragma unroll
                        for (int px = 0; px < 7; px++)
                            acc[cp][px] = ffma2(inr2[px + dx], wk, acc[cp][px]);
                    }
                }
            }
        }
    }
    if (active) {
#pragma unroll
        for (int cp = 0; cp < 4; cp++) {
            float* o0 = out + ((size_t)n * DCH + cobase + 2 * cp) * SS + y * S + x0;
            float* o1 = o0 + SS;
#pragma unroll
            for (int px = 0; px < 7; px++) {
                float2 f = unpack2(acc[cp][px]);
                o0[px] = f.x;
                o1[px] = f.y;
            }
        }
    }
}

// ---------------------------------------------------------------------------
// BN partial stats: grid (64, 2, NS). Atomic accumulate into g_stat[STAGE].
// Split stages (1,2,3) read two partial buffers and sum first.
// ---------------------------------------------------------------------------
template <int STAGE>
__global__ void bn_stats_part_kernel() {
    const float* inA = (STAGE == 0) ? g_buf1 : (STAGE == 1) ? g_buf3
                     : (STAGE == 2) ? g_buf5 : g_buf7;
    const float* inB = (STAGE == 1) ? g_buf3b
                     : (STAGE == 2) ? g_buf5b
                     : (STAGE == 3) ? g_buf7b : (const float*)0;
    const int S = (STAGE == 0) ? S1 : (STAGE == 1) ? S2 : S3;
    int ch  = blockIdx.x;
    int grp = blockIdx.y;
    int z   = blockIdx.z;
    int NS  = gridDim.z;
    int n0 = grp ? NQIMG : 0;
    int cnt = grp ? (NIMG - NQIMG) : NQIMG;
    int SS = S * S;
    long total = (long)cnt * SS;
    long len = (total + NS - 1) / NS;
    long i0 = (long)z * len;
    long i1 = min(total, i0 + len);
    float sum = 0.f, sumsq = 0.f;
    for (long i = i0 + threadIdx.x; i < i1; i += blockDim.x) {
        int n = n0 + (int)(i / SS);
        int p = (int)(i % SS);
        size_t idx = ((size_t)n * DCH + ch) * SS + p;
        float v = inA[idx];
        if (STAGE != 0) v += inB[idx];
        sum += v;
        sumsq += v * v;
    }
    __shared__ float s1[256], s2[256];
    int tid = threadIdx.x;
    s1[tid] = sum; s2[tid] = sumsq;
    __syncthreads();
    for (int off = 128; off > 0; off >>= 1) {
        if (tid < off) { s1[tid] += s1[tid + off]; s2[tid] += s2[tid + off]; }
        __syncthreads();
    }
    if (tid == 0) {
        atomicAdd(&g_stat[STAGE][grp][ch][0], s1[0]);
        atomicAdd(&g_stat[STAGE][grp][ch][1], s2[0]);
    }
}

template <int STAGE>
__global__ void bn_finalize_kernel(const float* __restrict__ g,
                                   const float* __restrict__ b) {
    int tid = threadIdx.x;
    if (tid >= 128) return;
    int grp = tid >> 6, ch = tid & 63;
    const int S = (STAGE == 0) ? S1 : (STAGE == 1) ? S2 : S3;
    long cnt = (long)(grp ? (NIMG - NQIMG) : NQIMG) * S * S;
    double m   = (double)g_stat[STAGE][grp][ch][0] / (double)cnt;
    double var = (double)g_stat[STAGE][grp][ch][1] / (double)cnt - m * m;
    double inv = 1.0 / sqrt(var + 1e-5);
    float a = g[ch] * (float)inv;
    g_bnA[grp * DCH + ch] = a;
    g_bnC[grp * DCH + ch] = b[ch] - (float)m * a;
}

// ---------------------------------------------------------------------------
// BN + LeakyReLU + 2x2 maxpool. STAGE 0: buf1(84)->buf2(42) single input.
// STAGE 1: (buf3+buf3b)(42)->buf4(21).
// ---------------------------------------------------------------------------
template <int STAGE>
__global__ void bn_pool_kernel() {
    const float* inA = (STAGE == 0) ? g_buf1 : g_buf3;
    const float* inB = (STAGE == 0) ? (const float*)0 : g_buf3b;
    float*      out = (STAGE == 0) ? g_buf2 : g_buf4;
    const int S  = (STAGE == 0) ? S1 : S2;
    const int So = S / 2;
    long total = (long)NIMG * DCH * So * So;
    long idx = (long)blockIdx.x * blockDim.x + threadIdx.x;
    if (idx >= total) return;
    int SoSo = So * So;
    int p  = (int)(idx % SoSo);
    long t = idx / SoSo;
    int ch = (int)(t % DCH);
    int n  = (int)(t / DCH);
    int grp = (n < NQIMG) ? 0 : 1;
    float a = g_bnA[grp * DCH + ch];
    float c = g_bnC[grp * DCH + ch];
    int yo = p / So, xo = p % So;
    size_t base = ((size_t)n * DCH + ch) * S * S;
    float m = -1e30f;
#pragma unroll
    for (int dy = 0; dy < 2; dy++)
#pragma unroll
        for (int dx = 0; dx < 2; dx++) {
            size_t q = base + (2 * yo + dy) * S + (2 * xo + dx);
            float x = inA[q];
            if (STAGE != 0) x += inB[q];
            float v = x * a + c;
            v = (v > 0.f) ? v : LRELU_SLOPE * v;
            m = fmaxf(m, v);
        }
    out[idx] = m;
}

// ---------------------------------------------------------------------------
// BN + LeakyReLU (no pool), paired partial inputs, S=21.
// STAGE 0: (buf5+buf5b)->buf6, 1: (buf7+buf7b)->buf8
// ---------------------------------------------------------------------------
template <int STAGE>
__global__ void bn_act_kernel() {
    const float* inA = (STAGE == 0) ? g_buf5 : g_buf7;
    const float* inB = (STAGE == 0) ? g_buf5b : g_buf7b;
    float*      out = (STAGE == 0) ? g_buf6 : g_buf8;
    long total = (long)NIMG * DCH * HW3;
    long idx = (long)blockIdx.x * blockDim.x + threadIdx.x;
    if (idx >= total) return;
    long t = idx / HW3;
    int ch = (int)(t % DCH);
    int n  = (int)(t / DCH);
    int grp = (n < NQIMG) ? 0 : 1;
    float v = (inA[idx] + inB[idx]) * g_bnA[grp * DCH + ch] + g_bnC[grp * DCH + ch];
    out[idx] = (v > 0.f) ? v : LRELU_SLOPE * v;
}

// ---------------------------------------------------------------------------
// L2-normalize + scatter to bf16 descriptor layouts.
// q: (bq, row(l) [512-pad], ch)  s: (sw, row(m=sh*441+l) [2304-pad], ch)
// ---------------------------------------------------------------------------
__global__ void normalize_kernel() {
    int warp = threadIdx.x >> 5;
    int lane = threadIdx.x & 31;
    int n = blockIdx.x;
    int l = blockIdx.y * 4 + warp;
    if (l >= HW3) return;
    const float* f = g_buf8 + (size_t)n * DCH * HW3;
    float x0 = f[lane * HW3 + l];
    float x1 = f[(lane + 32) * HW3 + l];
    float ss = x0 * x0 + x1 * x1;
#pragma unroll
    for (int off = 16; off > 0; off >>= 1)
        ss += __shfl_xor_sync(0xffffffffu, ss, off);
    float inv = 1.f / fmaxf(sqrtf(ss), 1e-12f);
    if (n < NQIMG) {
        __nv_bfloat16* dst = g_qbf + ((size_t)n * QPAD + l) * DCH;
        dst[lane]      = __float2bfloat16(x0 * inv);
        dst[lane + 32] = __float2bfloat16(x1 * inv);
    } else {
        int sn = n - NQIMG;
        int b  = sn / 25;
        int w  = (sn % 25) / 5;
        int sh = sn % 5;
        int sw = b * 5 + w;
        int m  = sh * HW3 + l;
        __nv_bfloat16* dst = g_sbf + ((size_t)sw * SPAD + m) * DCH;
        dst[lane]      = __float2bfloat16(x0 * inv);
        dst[lane + 32] = __float2bfloat16(x1 * inv);
    }
}

// ---------------------------------------------------------------------------
// Tensor-core similarity + fused top-3 + sum.
// Grid (mblk=2, w=5, bq=30), 512 threads = 16 warps; warp m-tile = 16 rows.
// C[m=441 rows][n=2205 cols] = q . s^T over k=64, bf16 mma, f32 accum.
// s tiles staged in XOR-swizzled smem (conflict-free fragment loads).
// ---------------------------------------------------------------------------
__global__ __launch_bounds__(512)
void sim_mma_kernel(float* __restrict__ out) {
    int mblk = blockIdx.x;
    int w    = blockIdx.y;
    int bq   = blockIdx.z;
    int sw   = (bq / 15) * 5 + w;
    int tid  = threadIdx.x;
    int warp = tid >> 5, lane = tid & 31;
    int g = lane >> 2, tg = lane & 3;

    int m0 = mblk * 256 + warp * 16;
    int r0 = m0 + g, r1 = r0 + 8;   // global q rows (may exceed 440)

    // A fragments (held in regs for the whole kernel)
    const __nv_bfloat16* qb = g_qbf + (size_t)bq * QPAD * DCH;
    u32 af[4][4];
#pragma unroll
    for (int kc = 0; kc < 4; kc++) {
        int c0 = kc * 16 + tg * 2;
        af[kc][0] = *(const u32*)(qb + (size_t)r0 * DCH + c0);
        af[kc][1] = *(const u32*)(qb + (size_t)r1 * DCH + c0);
        af[kc][2] = *(const u32*)(qb + (size_t)r0 * DCH + c0 + 8);
        af[kc][3] = *(const u32*)(qb + (size_t)r1 * DCH + c0 + 8);
    }

    float t0a = -1e30f, t1a = -1e30f, t2a = -1e30f;   // top3 row r0
    float t0b = -1e30f, t1b = -1e30f, t2b = -1e30f;   // top3 row r1

    __shared__ uint4 ssm[256 * 8];   // 256 s-rows x 128B, swizzled
    const uint4* sp = (const uint4*)(g_sbf + (size_t)sw * SPAD * DCH);

    for (int ch = 0; ch < 9; ch++) {
        __syncthreads();
        for (int i = tid; i < 2048; i += 512) {
            int n = i >> 3, j = i & 7;
            ssm[(n << 3) + (j ^ (n & 7))] = sp[ch * 2048 + i];
        }
        __syncthreads();
        int nbase_ch = ch * 256;
        int tmax = (ch == 8) ? 20 : 32;   // last chunk: cols beyond 2204 unused
        for (int t = 0; t < tmax; t++) {
            int nl = (t << 3) + g;        // this thread's B-fragment s-row
            const u32* srow = (const u32*)ssm + ((size_t)nl << 5);
            float c0 = 0.f, c1 = 0.f, c2 = 0.f, c3 = 0.f;
#pragma unroll
            for (int kc = 0; kc < 4; kc++) {
                u32 b0 = srow[(((kc * 2)     ^ g) << 2) + tg];
                u32 b1 = srow[(((kc * 2 + 1) ^ g) << 2) + tg];
                asm volatile(
                    "mma.sync.aligned.m16n8k16.row.col.f32.bf16.bf16.f32 "
                    "{%0,%1,%2,%3}, {%4,%5,%6,%7}, {%8,%9}, {%0,%1,%2,%3};"
                    : "+f"(c0), "+f"(c1), "+f"(c2), "+f"(c3)
                    : "r"(af[kc][0]), "r"(af[kc][1]), "r"(af[kc][2]), "r"(af[kc][3]),
                      "r"(b0), "r"(b1));
            }
            int col0 = nbase_ch + (t << 3) + tg * 2;
            if (col0 < MDIM)     { TOPK3(t0a, t1a, t2a, c0); TOPK3(t0b, t1b, t2b, c2); }
            if (col0 + 1 < MDIM) { TOPK3(t0a, t1a, t2a, c1); TOPK3(t0b, t1b, t2b, c3); }
        }
    }

    // merge top3 across the 4 quad lanes (same rows, disjoint cols)
#pragma unroll
    for (int d = 1; d < 4; d <<= 1) {
        float m0a = __shfl_xor_sync(0xffffffffu, t0a, d);
        float m1a = __shfl_xor_sync(0xffffffffu, t1a, d);
        float m2a = __shfl_xor_sync(0xffffffffu, t2a, d);
        TOPK3(t0a, t1a, t2a, m0a); TOPK3(t0a, t1a, t2a, m1a); TOPK3(t0a, t1a, t2a, m2a);
        float m0b = __shfl_xor_sync(0xffffffffu, t0b, d);
        float m1b = __shfl_xor_sync(0xffffffffu, t1b, d);
        float m2b = __shfl_xor_sync(0xffffffffu, t2b, d);
        TOPK3(t0b, t1b, t2b, m0b); TOPK3(t0b, t1b, t2b, m1b); TOPK3(t0b, t1b, t2b, m2b);
    }

    float v = 0.f;
    if (tg == 0) {
        if (r0 < HW3) v += t0a + t1a + t2a;
        if (r1 < HW3) v += t0b + t1b + t2b;
    }
#pragma unroll
    for (int off = 16; off > 0; off >>= 1)
        v += __shfl_down_sync(0xffffffffu, v, off);

    __shared__ float red[16];
    if (lane == 0) red[warp] = v;
    __syncthreads();
    if (warp == 0) {
        float x = (lane < 16) ? red[lane] : 0.f;
#pragma unroll
        for (int off = 8; off > 0; off >>= 1)
            x += __shfl_down_sync(0xffffffffu, x, off);
        if (lane == 0) atomicAdd(&out[bq * 5 + w], x);
    }
}

// ---------------------------------------------------------------------------
// Launcher
// ---------------------------------------------------------------------------
extern "C" void kernel_launch(void* const* d_in, const int* in_sizes, int n_in,
                              void* d_out, int out_size) {
    const float* query   = (const float*)d_in[0];
    const float* support = (const float*)d_in[1];
    const float* W1 = (const float*)d_in[2];
    const float* W2 = (const float*)d_in[3];
    const float* W3 = (const float*)d_in[4];
    const float* W4 = (const float*)d_in[5];
    const float* g1 = (const float*)d_in[6];
    const float* b1 = (const float*)d_in[7];
    const float* g2 = (const float*)d_in[8];
    const float* b2 = (const float*)d_in[9];
    const float* g3 = (const float*)d_in[10];
    const float* b3 = (const float*)d_in[11];
    const float* g4 = (const float*)d_in[12];
    const float* b4 = (const float*)d_in[13];
    float* out = (float*)d_out;

    zero_misc_kernel<<<1, 1024>>>(out);

    // layer 1: conv 3->64 @84, bn, lrelu, pool -> 42
    conv1_kernel<<<dim3(4, 80), 256>>>(query, support, W1);
    bn_stats_part_kernel<0><<<dim3(64, 2, 8), 256>>>();
    bn_finalize_kernel<0><<<1, 128>>>(g1, b1);
    {
        long total = (long)NIMG * DCH * S2 * S2;
        bn_pool_kernel<0><<<(int)((total + 255) / 256), 256>>>();
    }
    // layer 2: conv 64->64 @42 (K-split), bn, lrelu, pool -> 21
    conv64split_kernel<S2, 0><<<dim3(8, 80, 2), 256>>>(W2);
    bn_stats_part_kernel<1><<<dim3(64, 2, 4), 256>>>();
    bn_finalize_kernel<1><<<1, 128>>>(g2, b2);
    {
        long total = (long)NIMG * DCH * S3 * S3;
        bn_pool_kernel<1><<<(int)((total + 255) / 256), 256>>>();
    }
    // layer 3: conv 64->64 @21 (K-split), bn, lrelu
    conv64split_kernel<S3, 1><<<dim3(8, 80, 2), 64>>>(W3);
    bn_stats_part_kernel<2><<<dim3(64, 2, 2), 256>>>();
    bn_finalize_kernel<2><<<1, 128>>>(g3, b3);
    {
        long total = (long)NIMG * DCH * HW3;
        bn_act_kernel<0><<<(int)((total + 255) / 256), 256>>>();
    }
    // layer 4: conv 64->64 @21 (K-split), bn, lrelu
    conv64split_kernel<S3, 2><<<dim3(8, 80, 2), 64>>>(W4);
    bn_stats_part_kernel<3><<<dim3(64, 2, 2), 256>>>();
    bn_finalize_kernel<3><<<1, 128>>>(g4, b4);
    {
        long total = (long)NIMG * DCH * HW3;
        bn_act_kernel<1><<<(int)((total + 255) / 256), 256>>>();
    }
    // normalize + scatter (bf16 descriptors)
    normalize_kernel<<<dim3(80, 111), 128>>>();
    // tensor-core similarity + top-3 + reduce
    sim_mma_kernel<<<dim3(2, 5, 30), 512>>>(out);
}

// round 7
// speedup vs baseline: 2.5274x; 1.0188x over previous
#include <cuda_runtime.h>
#include <cuda_bf16.h>
#include <stdint.h>
#include <math.h>

#define NIMG   80
#define NQIMG  30
#define S1     84
#define S2     42
#define S3     21
#define DCH    64
#define HW3    (S3*S3)      // 441
#define MDIM   (5*HW3)      // 2205
#define QPAD   512
#define SPAD   2304
#define LRELU_SLOPE 0.2f

typedef unsigned long long ull;
typedef unsigned int u32;

__device__ float g_buf1[(size_t)NIMG*DCH*S1*S1];
__device__ float g_buf2[(size_t)NIMG*DCH*S2*S2];
__device__ float g_buf3[(size_t)NIMG*DCH*S2*S2];
__device__ float g_buf3b[(size_t)NIMG*DCH*S2*S2];
__device__ float g_buf4[(size_t)NIMG*DCH*S3*S3];
__device__ float g_buf5[(size_t)NIMG*DCH*S3*S3];
__device__ float g_buf5b[(size_t)NIMG*DCH*S3*S3];
__device__ float g_buf6[(size_t)NIMG*DCH*S3*S3];
__device__ float g_buf7[(size_t)NIMG*DCH*S3*S3];
__device__ float g_buf7b[(size_t)NIMG*DCH*S3*S3];
__device__ __nv_bfloat16 g_qbf[(size_t)NQIMG*QPAD*DCH];
__device__ __nv_bfloat16 g_sbf[(size_t)10*SPAD*DCH];
__device__ float g_stat[4][2][DCH][2];   // [stage][grp][ch][{sum,sumsq}]

// ---------------- helpers ----------------
__device__ __forceinline__ ull pack2(float lo, float hi) {
    ull r; asm("mov.b64 %0, {%1, %2};" : "=l"(r) : "f"(lo), "f"(hi)); return r;
}
__device__ __forceinline__ ull dup2(float x) {
    ull r; asm("mov.b64 %0, {%1, %2};" : "=l"(r) : "f"(x), "f"(x)); return r;
}
__device__ __forceinline__ ull ffma2(ull a, ull b, ull c) {
    ull d; asm("fma.rn.f32x2 %0, %1, %2, %3;" : "=l"(d) : "l"(a), "l"(b), "l"(c)); return d;
}
__device__ __forceinline__ float2 unpack2(ull v) {
    float2 f; asm("mov.b64 {%0, %1}, %2;" : "=f"(f.x), "=f"(f.y) : "l"(v)); return f;
}
__device__ __forceinline__ u32 bf2pack(float a, float b) {
    __nv_bfloat162 t = __floats2bfloat162_rn(a, b);
    return *(u32*)&t;
}
// stage stats -> (scale, shift) for one (grp, ch)
template <int STAGE>
__device__ __forceinline__ float2 bn_ac(int grp, int ch,
                                        const float* g, const float* b) {
    const int S = (STAGE == 0) ? S1 : (STAGE == 1) ? S2 : S3;
    float cnt = (float)((grp ? (NIMG - NQIMG) : NQIMG) * S * S);
    float m   = g_stat[STAGE][grp][ch][0] / cnt;
    float var = g_stat[STAGE][grp][ch][1] / cnt - m * m;
    float a = g[ch] * rsqrtf(var + 1e-5f);
    return make_float2(a, b[ch] - m * a);
}

#define TOPK3(t0, t1, t2, val)                                   \
    do { float _v = (val);                                       \
        if (_v > (t2)) {                                         \
            if (_v > (t0))      { (t2)=(t1); (t1)=(t0); (t0)=_v; } \
            else if (_v > (t1)) { (t2)=(t1); (t1)=_v; }          \
            else                { (t2)=_v; }                     \
        } } while (0)

// ---------------------------------------------------------------------------
__global__ void zero_misc_kernel(float* out) {
    int tid = threadIdx.x;
    float* st = &g_stat[0][0][0][0];
    if (tid < 1024) st[tid] = 0.f;
    if (tid < 150)  out[tid] = 0.f;
}

// ---------------------------------------------------------------------------
// conv1: 3 -> 64, 84x84 SAME.
// ---------------------------------------------------------------------------
__global__ __launch_bounds__(256)
void conv1_kernel(const float* __restrict__ q,
                  const float* __restrict__ s,
                  const float* __restrict__ W1) {
    __shared__ float img[3 * 23 * 86];
    __shared__ float wsm[64 * 27];
    int tid = threadIdx.x, n = blockIdx.y, ty = blockIdx.x;
    const float* src = (n < NQIMG) ? q + (size_t)n * 3 * S1 * S1
                                   : s + (size_t)(n - NQIMG) * 3 * S1 * S1;
    for (int i = tid; i < 64 * 27; i += 256) wsm[i] = W1[i];
    for (int i = tid; i < 3 * 23 * 86; i += 256) {
        int ci = i / (23 * 86);
        int r  = (i / 86) % 23;
        int c  = i % 86;
        int gy = ty * 21 + r - 1, gx = c - 1;
        img[i] = ((unsigned)gy < S1 && (unsigned)gx < S1)
                     ? src[ci * S1 * S1 + gy * S1 + gx] : 0.f;
    }
    __syncthreads();
    if (tid >= 252) return;
    int yl = tid / 12, x0 = (tid % 12) * 7;
    int gy = ty * 21 + yl;

    for (int cb = 0; cb < 8; cb++) {
        float acc[8][7];
#pragma unroll
        for (int c = 0; c < 8; c++)
#pragma unroll
            for (int px = 0; px < 7; px++) acc[c][px] = 0.f;
#pragma unroll
        for (int ci = 0; ci < 3; ci++) {
            float inr[27];
#pragma unroll
            for (int r = 0; r < 3; r++)
#pragma unroll
                for (int c = 0; c < 9; c++)
                    inr[r * 9 + c] = img[ci * 23 * 86 + (yl + r) * 86 + x0 + c];
#pragma unroll
            for (int k = 0; k < 9; k++) {
                int dy = k / 3, dx = k % 3;
                float wk[8];
#pragma unroll
                for (int c = 0; c < 8; c++)
                    wk[c] = wsm[(cb * 8 + c) * 27 + ci * 9 + k];
#pragma unroll
                for (int c = 0; c < 8; c++)
#pragma unroll
                    for (int px = 0; px < 7; px++)
                        acc[c][px] += inr[dy * 9 + px + dx] * wk[c];
            }
        }
#pragma unroll
        for (int c = 0; c < 8; c++) {
            int co = cb * 8 + c;
            float* op = g_buf1 + ((size_t)n * DCH + co) * (S1 * S1) + gy * S1 + x0;
#pragma unroll
            for (int px = 0; px < 7; px++) op[px] = acc[c][px];
        }
    }
}

// ---------------------------------------------------------------------------
// conv 64->64 @42, K-split halves. (single image per block, 256 thr)
// ---------------------------------------------------------------------------
__global__ __launch_bounds__(256)
void conv42_kernel(const float* __restrict__ W) {
    constexpr int S = S2, SP = S + 2, SPSP = SP * SP, SS = S * S;
    constexpr int STRIPS = S / 7, NPOS = STRIPS * S, NT = 256;

    __shared__ float plane[2][SPSP];
    __shared__ ull wsm2[4 * 32 * 9];

    int tid = threadIdx.x;
    int n = blockIdx.y;
    int ks = blockIdx.z;
    int ci0 = ks * 32;
    int cobase = blockIdx.x * 8;
    float* out = ks ? g_buf3b : g_buf3;

    for (int i = tid; i < 4 * 32 * 9; i += NT) {
        int cp = i / 288, rem = i % 288;
        int ic = rem / 9, k = rem % 9;
        float w0 = W[(cobase + cp * 2) * 576 + (ci0 + ic) * 9 + k];
        float w1 = W[(cobase + cp * 2 + 1) * 576 + (ci0 + ic) * 9 + k];
        wsm2[i] = pack2(w0, w1);
    }

    bool active = tid < NPOS;
    int y = tid / STRIPS, x0 = (tid % STRIPS) * 7;

    ull acc[4][7];
#pragma unroll
    for (int cp = 0; cp < 4; cp++)
#pragma unroll
        for (int px = 0; px < 7; px++) acc[cp][px] = 0ull;

    const float* ibase = g_buf2 + (size_t)n * DCH * SS + (size_t)ci0 * SS;

    for (int i = tid; i < SPSP; i += NT) {
        int yy = i / SP - 1, xx = i % SP - 1;
        plane[0][i] = ((unsigned)yy < S && (unsigned)xx < S)
                          ? ibase[yy * S + xx] : 0.f;
    }

    for (int ic = 0; ic < 32; ic++) {
        __syncthreads();
        if (ic + 1 < 32) {
            const float* src = ibase + (ic + 1) * SS;
            int bidx = (ic + 1) & 1;
            for (int i = tid; i < SPSP; i += NT) {
                int yy = i / SP - 1, xx = i % SP - 1;
                plane[bidx][i] = ((unsigned)yy < S && (unsigned)xx < S)
                                     ? src[yy * S + xx] : 0.f;
            }
        }
        if (active) {
            const float* pb = plane[ic & 1];
#pragma unroll
            for (int dy = 0; dy < 3; dy++) {
                ull inr2[9];
#pragma unroll
                for (int c = 0; c < 9; c++)
                    inr2[c] = dup2(pb[(y + dy) * SP + x0 + c]);
#pragma unroll
                for (int dx = 0; dx < 3; dx++) {
                    int k = dy * 3 + dx;
#pragma unroll
                    for (int cp = 0; cp < 4; cp++) {
                        ull wk = wsm2[(cp * 32 + ic) * 9 + k];
#pragma unroll
                        for (int px = 0; px < 7; px++)
                            acc[cp][px] = ffma2(inr2[px + dx], wk, acc[cp][px]);
                    }
                }
            }
        }
    }
    if (active) {
#pragma unroll
        for (int cp = 0; cp < 4; cp++) {
            float* o0 = out + ((size_t)n * DCH + cobase + 2 * cp) * SS + y * S + x0;
            float* o1 = o0 + SS;
#pragma unroll
            for (int px = 0; px < 7; px++) {
                float2 f = unpack2(acc[cp][px]);
                o0[px] = f.x;
                o1[px] = f.y;
            }
        }
    }
}

// ---------------------------------------------------------------------------
// conv 64->64 @21, K-split halves, TWO images per block (128 thr).
// STAGE: 1 buf4 -> buf5/5b, 2 buf6 -> buf7/7b
// ---------------------------------------------------------------------------
template <int STAGE>
__global__ __launch_bounds__(128)
void conv21_kernel(const float* __restrict__ W) {
    constexpr int S = S3, SP = S + 2, SPSP = SP * SP, SS = S * S;
    constexpr int STRIPS = S / 7, NPOS = STRIPS * S;   // 63
    const float* in = (STAGE == 1) ? g_buf4 : g_buf6;
    float* outA = (STAGE == 1) ? g_buf5 : g_buf7;
    float* outB = (STAGE == 1) ? g_buf5b : g_buf7b;

    __shared__ float plane[2][2][SPSP];   // [img][buf][...]
    __shared__ ull wsm2[4 * 32 * 9];

    int tid = threadIdx.x;
    int img = tid >> 6, ltid = tid & 63;
    int n = blockIdx.y * 2 + img;
    int ks = blockIdx.z;
    int ci0 = ks * 32;
    int cobase = blockIdx.x * 8;
    float* out = ks ? outB : outA;

    for (int i = tid; i < 4 * 32 * 9; i += 128) {
        int cp = i / 288, rem = i % 288;
        int ic = rem / 9, k = rem % 9;
        float w0 = W[(cobase + cp * 2) * 576 + (ci0 + ic) * 9 + k];
        float w1 = W[(cobase + cp * 2 + 1) * 576 + (ci0 + ic) * 9 + k];
        wsm2[i] = pack2(w0, w1);
    }

    bool active = ltid < NPOS;
    int y = ltid / STRIPS, x0 = (ltid % STRIPS) * 7;

    ull acc[4][7];
#pragma unroll
    for (int cp = 0; cp < 4; cp++)
#pragma unroll
        for (int px = 0; px < 7; px++) acc[cp][px] = 0ull;

    const float* ibase = in + (size_t)n * DCH * SS + (size_t)ci0 * SS;

    for (int i = ltid; i < SPSP; i += 64) {
        int yy = i / SP - 1, xx = i % SP - 1;
        plane[img][0][i] = ((unsigned)yy < S && (unsigned)xx < S)
                               ? ibase[yy * S + xx] : 0.f;
    }

    for (int ic = 0; ic < 32; ic++) {
        __syncthreads();
        if (ic + 1 < 32) {
            const float* src = ibase + (ic + 1) * SS;
            int bidx = (ic + 1) & 1;
            for (int i = ltid; i < SPSP; i += 64) {
                int yy = i / SP - 1, xx = i % SP - 1;
                plane[img][bidx][i] = ((unsigned)yy < S && (unsigned)xx < S)
                                          ? src[yy * S + xx] : 0.f;
            }
        }
        if (active) {
            const float* pb = plane[img][ic & 1];
#pragma unroll
            for (int dy = 0; dy < 3; dy++) {
                ull inr2[9];
#pragma unroll
                for (int c = 0; c < 9; c++)
                    inr2[c] = dup2(pb[(y + dy) * SP + x0 + c]);
#pragma unroll
                for (int dx = 0; dx < 3; dx++) {
                    int k = dy * 3 + dx;
#pragma unroll
                    for (int cp = 0; cp < 4; cp++) {
                        ull wk = wsm2[(cp * 32 + ic) * 9 + k];
#pragma unroll
                        for (int px = 0; px < 7; px++)
                            acc[cp][px] = ffma2(inr2[px + dx], wk, acc[cp][px]);
                    }
                }
            }
        }
    }
    if (active) {
#pragma unroll
        for (int cp = 0; cp < 4; cp++) {
            float* o0 = out + ((size_t)n * DCH + cobase + 2 * cp) * SS + y * S + x0;
            float* o1 = o0 + SS;
#pragma unroll
            for (int px = 0; px < 7; px++) {
                float2 f = unpack2(acc[cp][px]);
                o0[px] = f.x;
                o1[px] = f.y;
            }
        }
    }
}

// ---------------------------------------------------------------------------
// BN partial stats -> g_stat[STAGE] via atomics (split stages merge partials).
// ---------------------------------------------------------------------------
template <int STAGE>
__global__ void bn_stats_part_kernel() {
    const float* inA = (STAGE == 0) ? g_buf1 : (STAGE == 1) ? g_buf3
                     : (STAGE == 2) ? g_buf5 : g_buf7;
    const float* inB = (STAGE == 1) ? g_buf3b
                     : (STAGE == 2) ? g_buf5b
                     : (STAGE == 3) ? g_buf7b : (const float*)0;
    const int S = (STAGE == 0) ? S1 : (STAGE == 1) ? S2 : S3;
    int ch  = blockIdx.x;
    int grp = blockIdx.y;
    int z   = blockIdx.z;
    int NS  = gridDim.z;
    int n0 = grp ? NQIMG : 0;
    int cnt = grp ? (NIMG - NQIMG) : NQIMG;
    int SS = S * S;
    long total = (long)cnt * SS;
    long len = (total + NS - 1) / NS;
    long i0 = (long)z * len;
    long i1 = min(total, i0 + len);
    float sum = 0.f, sumsq = 0.f;
    for (long i = i0 + threadIdx.x; i < i1; i += blockDim.x) {
        int n = n0 + (int)(i / SS);
        int p = (int)(i % SS);
        size_t idx = ((size_t)n * DCH + ch) * SS + p;
        float v = inA[idx];
        if (STAGE != 0) v += inB[idx];
        sum += v;
        sumsq += v * v;
    }
    __shared__ float s1[256], s2[256];
    int tid = threadIdx.x;
    s1[tid] = sum; s2[tid] = sumsq;
    __syncthreads();
    for (int off = 128; off > 0; off >>= 1) {
        if (tid < off) { s1[tid] += s1[tid + off]; s2[tid] += s2[tid + off]; }
        __syncthreads();
    }
    if (tid == 0) {
        atomicAdd(&g_stat[STAGE][grp][ch][0], s1[0]);
        atomicAdd(&g_stat[STAGE][grp][ch][1], s2[0]);
    }
}

// ---------------------------------------------------------------------------
// BN(inline A/C) + LeakyReLU + 2x2 maxpool.
// STAGE 0: buf1(84)->buf2(42). STAGE 1: (buf3+buf3b)(42)->buf4(21).
// ---------------------------------------------------------------------------
template <int STAGE>
__global__ __launch_bounds__(256)
void bn_pool_kernel(const float* __restrict__ g, const float* __restrict__ b) {
    const float* inA = (STAGE == 0) ? g_buf1 : g_buf3;
    const float* inB = (STAGE == 0) ? (const float*)0 : g_buf3b;
    float*      out = (STAGE == 0) ? g_buf2 : g_buf4;
    const int S  = (STAGE == 0) ? S1 : S2;
    const int So = S / 2;
    __shared__ float sA[128], sC[128];
    if (threadIdx.x < 128) {
        float2 ac = bn_ac<STAGE>(threadIdx.x >> 6, threadIdx.x & 63, g, b);
        sA[threadIdx.x] = ac.x; sC[threadIdx.x] = ac.y;
    }
    __syncthreads();
    long total = (long)NIMG * DCH * So * So;
    long idx = (long)blockIdx.x * blockDim.x + threadIdx.x;
    if (idx >= total) return;
    int SoSo = So * So;
    int p  = (int)(idx % SoSo);
    long t = idx / SoSo;
    int ch = (int)(t % DCH);
    int n  = (int)(t / DCH);
    int gi = ((n < NQIMG) ? 0 : 64) + ch;
    float a = sA[gi], c = sC[gi];
    int yo = p / So, xo = p % So;
    size_t base = ((size_t)n * DCH + ch) * S * S;
    float m = -1e30f;
#pragma unroll
    for (int dy = 0; dy < 2; dy++)
#pragma unroll
        for (int dx = 0; dx < 2; dx++) {
            size_t q = base + (2 * yo + dy) * S + (2 * xo + dx);
            float x = inA[q];
            if (STAGE != 0) x += inB[q];
            float v = x * a + c;
            v = (v > 0.f) ? v : LRELU_SLOPE * v;
            m = fmaxf(m, v);
        }
    out[idx] = m;
}

// ---------------------------------------------------------------------------
// BN(inline A/C, stage2) + LeakyReLU: (buf5+buf5b)->buf6, S=21.
// ---------------------------------------------------------------------------
__global__ __launch_bounds__(256)
void bn_act_kernel(const float* __restrict__ g, const float* __restrict__ b) {
    __shared__ float sA[128], sC[128];
    if (threadIdx.x < 128) {
        float2 ac = bn_ac<2>(threadIdx.x >> 6, threadIdx.x & 63, g, b);
        sA[threadIdx.x] = ac.x; sC[threadIdx.x] = ac.y;
    }
    __syncthreads();
    long total = (long)NIMG * DCH * HW3;
    long idx = (long)blockIdx.x * blockDim.x + threadIdx.x;
    if (idx >= total) return;
    long t = idx / HW3;
    int ch = (int)(t % DCH);
    int n  = (int)(t / DCH);
    int gi = ((n < NQIMG) ? 0 : 64) + ch;
    float v = (g_buf5[idx] + g_buf5b[idx]) * sA[gi] + sC[gi];
    g_buf6[idx] = (v > 0.f) ? v : LRELU_SLOPE * v;
}

// ---------------------------------------------------------------------------
// Fused: BN(stage3) + LeakyReLU + L2-normalize + bf16 scatter.
// Thread = (image n, position l). Channel loads coalesced; 64 vals in regs.
// grid (80, 3), block 147.
// ---------------------------------------------------------------------------
__global__ __launch_bounds__(160)
void bn_norm_kernel(const float* __restrict__ g, const float* __restrict__ b) {
    int n = blockIdx.x;
    int l = blockIdx.y * 147 + threadIdx.x;
    int grp = (n < NQIMG) ? 0 : 1;
    __shared__ float sA[64], sC[64];
    if (threadIdx.x < 64) {
        float2 ac = bn_ac<3>(grp, threadIdx.x, g, b);
        sA[threadIdx.x] = ac.x; sC[threadIdx.x] = ac.y;
    }
    __syncthreads();
    if (threadIdx.x >= 147 || l >= HW3) return;

    const float* pa = g_buf7  + (size_t)n * DCH * HW3 + l;
    const float* pb = g_buf7b + (size_t)n * DCH * HW3 + l;
    float v[64];
    float ss = 0.f;
#pragma unroll
    for (int ch = 0; ch < 64; ch++) {
        float x = (pa[ch * HW3] + pb[ch * HW3]) * sA[ch] + sC[ch];
        x = (x > 0.f) ? x : LRELU_SLOPE * x;
        v[ch] = x;
        ss += x * x;
    }
    float inv = 1.f / fmaxf(sqrtf(ss), 1e-12f);

    __nv_bfloat16* dst;
    if (n < NQIMG) {
        dst = g_qbf + ((size_t)n * QPAD + l) * DCH;
    } else {
        int sn = n - NQIMG;
        int bb = sn / 25;
        int w  = (sn % 25) / 5;
        int sh = sn % 5;
        int sw = bb * 5 + w;
        int m  = sh * HW3 + l;
        dst = g_sbf + ((size_t)sw * SPAD + m) * DCH;
    }
#pragma unroll
    for (int c8 = 0; c8 < 64; c8 += 8) {
        uint4 u;
        u.x = bf2pack(v[c8 + 0] * inv, v[c8 + 1] * inv);
        u.y = bf2pack(v[c8 + 2] * inv, v[c8 + 3] * inv);
        u.z = bf2pack(v[c8 + 4] * inv, v[c8 + 5] * inv);
        u.w = bf2pack(v[c8 + 6] * inv, v[c8 + 7] * inv);
        *(uint4*)(dst + c8) = u;
    }
}

// ---------------------------------------------------------------------------
// Tensor-core similarity + fused top-3 + sum. (unchanged from round 6)
// ---------------------------------------------------------------------------
__global__ __launch_bounds__(512)
void sim_mma_kernel(float* __restrict__ out) {
    int mblk = blockIdx.x;
    int w    = blockIdx.y;
    int bq   = blockIdx.z;
    int sw   = (bq / 15) * 5 + w;
    int tid  = threadIdx.x;
    int warp = tid >> 5, lane = tid & 31;
    int g = lane >> 2, tg = lane & 3;

    int m0 = mblk * 256 + warp * 16;
    int r0 = m0 + g, r1 = r0 + 8;

    const __nv_bfloat16* qb = g_qbf + (size_t)bq * QPAD * DCH;
    u32 af[4][4];
#pragma unroll
    for (int kc = 0; kc < 4; kc++) {
        int c0 = kc * 16 + tg * 2;
        af[kc][0] = *(const u32*)(qb + (size_t)r0 * DCH + c0);
        af[kc][1] = *(const u32*)(qb + (size_t)r1 * DCH + c0);
        af[kc][2] = *(const u32*)(qb + (size_t)r0 * DCH + c0 + 8);
        af[kc][3] = *(const u32*)(qb + (size_t)r1 * DCH + c0 + 8);
    }

    float t0a = -1e30f, t1a = -1e30f, t2a = -1e30f;
    float t0b = -1e30f, t1b = -1e30f, t2b = -1e30f;

    __shared__ uint4 ssm[256 * 8];
    const uint4* sp = (const uint4*)(g_sbf + (size_t)sw * SPAD * DCH);

    for (int ch = 0; ch < 9; ch++) {
        __syncthreads();
        for (int i = tid; i < 2048; i += 512) {
            int nn = i >> 3, j = i & 7;
            ssm[(nn << 3) + (j ^ (nn & 7))] = sp[ch * 2048 + i];
        }
        __syncthreads();
        int nbase_ch = ch * 256;
        int tmax = (ch == 8) ? 20 : 32;
        for (int t = 0; t < tmax; t++) {
            int nl = (t << 3) + g;
            const u32* srow = (const u32*)ssm + ((size_t)nl << 5);
            float c0 = 0.f, c1 = 0.f, c2 = 0.f, c3 = 0.f;
#pragma unroll
            for (int kc = 0; kc < 4; kc++) {
                u32 b0 = srow[(((kc * 2)     ^ g) << 2) + tg];
                u32 b1 = srow[(((kc * 2 + 1) ^ g) << 2) + tg];
                asm volatile(
                    "mma.sync.aligned.m16n8k16.row.col.f32.bf16.bf16.f32 "
                    "{%0,%1,%2,%3}, {%4,%5,%6,%7}, {%8,%9}, {%0,%1,%2,%3};"
                    : "+f"(c0), "+f"(c1), "+f"(c2), "+f"(c3)
                    : "r"(af[kc][0]), "r"(af[kc][1]), "r"(af[kc][2]), "r"(af[kc][3]),
                      "r"(b0), "r"(b1));
            }
            int col0 = nbase_ch + (t << 3) + tg * 2;
            if (col0 < MDIM)     { TOPK3(t0a, t1a, t2a, c0); TOPK3(t0b, t1b, t2b, c2); }
            if (col0 + 1 < MDIM) { TOPK3(t0a, t1a, t2a, c1); TOPK3(t0b, t1b, t2b, c3); }
        }
    }

#pragma unroll
    for (int d = 1; d < 4; d <<= 1) {
        float m0a = __shfl_xor_sync(0xffffffffu, t0a, d);
        float m1a = __shfl_xor_sync(0xffffffffu, t1a, d);
        float m2a = __shfl_xor_sync(0xffffffffu, t2a, d);
        TOPK3(t0a, t1a, t2a, m0a); TOPK3(t0a, t1a, t2a, m1a); TOPK3(t0a, t1a, t2a, m2a);
        float m0b = __shfl_xor_sync(0xffffffffu, t0b, d);
        float m1b = __shfl_xor_sync(0xffffffffu, t1b, d);
        float m2b = __shfl_xor_sync(0xffffffffu, t2b, d);
        TOPK3(t0b, t1b, t2b, m0b); TOPK3(t0b, t1b, t2b, m1b); TOPK3(t0b, t1b, t2b, m2b);
    }

    float v = 0.f;
    if (tg == 0) {
        if (r0 < HW3) v += t0a + t1a + t2a;
        if (r1 < HW3) v += t0b + t1b + t2b;
    }
#pragma unroll
    for (int off = 16; off > 0; off >>= 1)
        v += __shfl_down_sync(0xffffffffu, v, off);

    __shared__ float red[16];
    if (lane == 0) red[warp] = v;
    __syncthreads();
    if (warp == 0) {
        float x = (lane < 16) ? red[lane] : 0.f;
#pragma unroll
        for (int off = 8; off > 0; off >>= 1)
            x += __shfl_down_sync(0xffffffffu, x, off);
        if (lane == 0) atomicAdd(&out[bq * 5 + w], x);
    }
}

// ---------------------------------------------------------------------------
// Launcher
// ---------------------------------------------------------------------------
extern "C" void kernel_launch(void* const* d_in, const int* in_sizes, int n_in,
                              void* d_out, int out_size) {
    const float* query   = (const float*)d_in[0];
    const float* support = (const float*)d_in[1];
    const float* W1 = (const float*)d_in[2];
    const float* W2 = (const float*)d_in[3];
    const float* W3 = (const float*)d_in[4];
    const float* W4 = (const float*)d_in[5];
    const float* g1 = (const float*)d_in[6];
    const float* b1 = (const float*)d_in[7];
    const float* g2 = (const float*)d_in[8];
    const float* b2 = (const float*)d_in[9];
    const float* g3 = (const float*)d_in[10];
    const float* b3 = (const float*)d_in[11];
    const float* g4 = (const float*)d_in[12];
    const float* b4 = (const float*)d_in[13];
    float* out = (float*)d_out;

    zero_misc_kernel<<<1, 1024>>>(out);

    // layer 1
    conv1_kernel<<<dim3(4, 80), 256>>>(query, support, W1);
    bn_stats_part_kernel<0><<<dim3(64, 2, 8), 256>>>();
    {
        long total = (long)NIMG * DCH * S2 * S2;
        bn_pool_kernel<0><<<(int)((total + 255) / 256), 256>>>(g1, b1);
    }
    // layer 2
    conv42_kernel<<<dim3(8, 80, 2), 256>>>(W2);
    bn_stats_part_kernel<1><<<dim3(64, 2, 4), 256>>>();
    {
        long total = (long)NIMG * DCH * S3 * S3;
        bn_pool_kernel<1><<<(int)((total + 255) / 256), 256>>>(g2, b2);
    }
    // layer 3
    conv21_kernel<1><<<dim3(8, 40, 2), 128>>>(W3);
    bn_stats_part_kernel<2><<<dim3(64, 2, 2), 256>>>();
    {
        long total = (long)NIMG * DCH * HW3;
        bn_act_kernel<<<(int)((total + 255) / 256), 256>>>(g3, b3);
    }
    // layer 4
    conv21_kernel<2><<<dim3(8, 40, 2), 128>>>(W4);
    bn_stats_part_kernel<3><<<dim3(64, 2, 2), 256>>>();
    // fused bn + lrelu + normalize + bf16 scatter
    bn_norm_kernel<<<dim3(80, 3), 160>>>(g4, b4);
    // tensor-core similarity
    sim_mma_kernel<<<dim3(2, 5, 30), 512>>>(out);
}

// round 16
// speedup vs baseline: 2.5358x; 1.0033x over previous
#include <cuda_runtime.h>
#include <cuda_bf16.h>
#include <stdint.h>
#include <math.h>

#define NIMG   80
#define NQIMG  30
#define S1     84
#define S2     42
#define S3     21
#define DCH    64
#define HW3    (S3*S3)      // 441
#define MDIM   (5*HW3)      // 2205
#define QPAD   512
#define SPAD   2304
#define LRELU_SLOPE 0.2f

typedef unsigned long long ull;
typedef unsigned int u32;

__device__ float g_buf1[(size_t)NIMG*DCH*S1*S1];
__device__ float g_buf2[(size_t)NIMG*DCH*S2*S2];
__device__ float g_buf3[(size_t)NIMG*DCH*S2*S2];   // conv2 partial ks=0
__device__ float g_buf3b[(size_t)NIMG*DCH*S2*S2];  // conv2 partial ks=1
__device__ float g_buf4[(size_t)NIMG*DCH*S3*S3];
__device__ float g_buf5[(size_t)NIMG*DCH*S3*S3];
__device__ float g_buf5b[(size_t)NIMG*DCH*S3*S3];
__device__ float g_buf6[(size_t)NIMG*DCH*S3*S3];
__device__ float g_buf7[(size_t)NIMG*DCH*S3*S3];
__device__ float g_buf7b[(size_t)NIMG*DCH*S3*S3];
__device__ __nv_bfloat16 g_qbf[(size_t)NQIMG*QPAD*DCH];
__device__ __nv_bfloat16 g_sbf[(size_t)10*SPAD*DCH];
__device__ float g_stat[4][2][DCH][2];   // [stage][grp][ch][{sum,sumsq}]

// ---------------- helpers ----------------
__device__ __forceinline__ ull pack2(float lo, float hi) {
    ull r; asm("mov.b64 %0, {%1, %2};" : "=l"(r) : "f"(lo), "f"(hi)); return r;
}
__device__ __forceinline__ ull dup2(float x) {
    ull r; asm("mov.b64 %0, {%1, %2};" : "=l"(r) : "f"(x), "f"(x)); return r;
}
__device__ __forceinline__ ull ffma2(ull a, ull b, ull c) {
    ull d; asm("fma.rn.f32x2 %0, %1, %2, %3;" : "=l"(d) : "l"(a), "l"(b), "l"(c)); return d;
}
__device__ __forceinline__ float2 unpack2(ull v) {
    float2 f; asm("mov.b64 {%0, %1}, %2;" : "=f"(f.x), "=f"(f.y) : "l"(v)); return f;
}
__device__ __forceinline__ u32 bf2pack(float a, float b) {
    __nv_bfloat162 t = __floats2bfloat162_rn(a, b);
    return *(u32*)&t;
}
// stage stats -> (scale, shift) for one (grp, ch)
template <int STAGE>
__device__ __forceinline__ float2 bn_ac(int grp, int ch,
                                        const float* g, const float* b) {
    const int S = (STAGE == 0) ? S1 : (STAGE == 1) ? S2 : S3;
    float cnt = (float)((grp ? (NIMG - NQIMG) : NQIMG) * S * S);
    float m   = g_stat[STAGE][grp][ch][0] / cnt;
    float var = g_stat[STAGE][grp][ch][1] / cnt - m * m;
    float a = g[ch] * rsqrtf(var + 1e-5f);
    return make_float2(a, b[ch] - m * a);
}

#define TOPK3(t0, t1, t2, val)                                   \
    do { float _v = (val);                                       \
        if (_v > (t2)) {                                         \
            if (_v > (t0))      { (t2)=(t1); (t1)=(t0); (t0)=_v; } \
            else if (_v > (t1)) { (t2)=(t1); (t1)=_v; }          \
            else                { (t2)=_v; }                     \
        } } while (0)

// ---------------------------------------------------------------------------
__global__ void zero_misc_kernel(float* out) {
    int tid = threadIdx.x;
    float* st = &g_stat[0][0][0][0];
    if (tid < 1024) st[tid] = 0.f;
    if (tid < 150)  out[tid] = 0.f;
}

// ---------------------------------------------------------------------------
// conv1: 3 -> 64, 84x84 SAME. (r7 proven)
// ---------------------------------------------------------------------------
__global__ __launch_bounds__(256)
void conv1_kernel(const float* __restrict__ q,
                  const float* __restrict__ s,
                  const float* __restrict__ W1) {
    __shared__ float img[3 * 23 * 86];
    __shared__ float wsm[64 * 27];
    int tid = threadIdx.x, n = blockIdx.y, ty = blockIdx.x;
    const float* src = (n < NQIMG) ? q + (size_t)n * 3 * S1 * S1
                                   : s + (size_t)(n - NQIMG) * 3 * S1 * S1;
    for (int i = tid; i < 64 * 27; i += 256) wsm[i] = W1[i];
    for (int i = tid; i < 3 * 23 * 86; i += 256) {
        int ci = i / (23 * 86);
        int r  = (i / 86) % 23;
        int c  = i % 86;
        int gy = ty * 21 + r - 1, gx = c - 1;
        img[i] = ((unsigned)gy < S1 && (unsigned)gx < S1)
                     ? src[ci * S1 * S1 + gy * S1 + gx] : 0.f;
    }
    __syncthreads();
    if (tid >= 252) return;
    int yl = tid / 12, x0 = (tid % 12) * 7;
    int gy = ty * 21 + yl;

    for (int cb = 0; cb < 8; cb++) {
        float acc[8][7];
#pragma unroll
        for (int c = 0; c < 8; c++)
#pragma unroll
            for (int px = 0; px < 7; px++) acc[c][px] = 0.f;
#pragma unroll
        for (int ci = 0; ci < 3; ci++) {
            float inr[27];
#pragma unroll
            for (int r = 0; r < 3; r++)
#pragma unroll
                for (int c = 0; c < 9; c++)
                    inr[r * 9 + c] = img[ci * 23 * 86 + (yl + r) * 86 + x0 + c];
#pragma unroll
            for (int k = 0; k < 9; k++) {
                int dy = k / 3, dx = k % 3;
                float wk[8];
#pragma unroll
                for (int c = 0; c < 8; c++)
                    wk[c] = wsm[(cb * 8 + c) * 27 + ci * 9 + k];
#pragma unroll
                for (int c = 0; c < 8; c++)
#pragma unroll
                    for (int px = 0; px < 7; px++)
                        acc[c][px] += inr[dy * 9 + px + dx] * wk[c];
            }
        }
#pragma unroll
        for (int c = 0; c < 8; c++) {
            int co = cb * 8 + c;
            float* op = g_buf1 + ((size_t)n * DCH + co) * (S1 * S1) + gy * S1 + x0;
#pragma unroll
            for (int px = 0; px < 7; px++) op[px] = acc[c][px];
        }
    }
}

// ---------------------------------------------------------------------------
// conv 64->64 @42, f32x2, K-split halves (blockIdx.z), 2 co-pairs per thread
// (4 output channels per block). grid (16, 80, 2), 256 thr.
// buf2 -> buf3/buf3b partials.
// ---------------------------------------------------------------------------
__global__ __launch_bounds__(256)
void conv42_kernel(const float* __restrict__ W) {
    constexpr int S = S2, SP = S + 2, SPSP = SP * SP, SS = S * S;
    constexpr int STRIPS = S / 7, NPOS = STRIPS * S, NT = 256;

    __shared__ float plane[2][SPSP];
    __shared__ ull wsm2[2 * 32 * 9];

    int tid = threadIdx.x;
    int n = blockIdx.y;
    int ks = blockIdx.z;
    int ci0 = ks * 32;
    int cobase = blockIdx.x * 4;
    float* out = ks ? g_buf3b : g_buf3;

    for (int i = tid; i < 2 * 32 * 9; i += NT) {
        int cp = i / 288, rem = i % 288;
        int ic = rem / 9, k = rem % 9;
        float w0 = W[(cobase + cp * 2) * 576 + (ci0 + ic) * 9 + k];
        float w1 = W[(cobase + cp * 2 + 1) * 576 + (ci0 + ic) * 9 + k];
        wsm2[i] = pack2(w0, w1);
    }

    bool active = tid < NPOS;
    int y = tid / STRIPS, x0 = (tid % STRIPS) * 7;

    ull acc[2][7];
#pragma unroll
    for (int cp = 0; cp < 2; cp++)
#pragma unroll
        for (int px = 0; px < 7; px++) acc[cp][px] = 0ull;

    const float* ibase = g_buf2 + (size_t)n * DCH * SS + (size_t)ci0 * SS;

    for (int i = tid; i < SPSP; i += NT) {
        int yy = i / SP - 1, xx = i % SP - 1;
        plane[0][i] = ((unsigned)yy < S && (unsigned)xx < S)
                          ? ibase[yy * S + xx] : 0.f;
    }

    for (int ic = 0; ic < 32; ic++) {
        __syncthreads();
        if (ic + 1 < 32) {
            const float* src = ibase + (ic + 1) * SS;
            int bidx = (ic + 1) & 1;
            for (int i = tid; i < SPSP; i += NT) {
                int yy = i / SP - 1, xx = i % SP - 1;
                plane[bidx][i] = ((unsigned)yy < S && (unsigned)xx < S)
                                     ? src[yy * S + xx] : 0.f;
            }
        }
        if (active) {
            const float* pb = plane[ic & 1];
#pragma unroll
            for (int dy = 0; dy < 3; dy++) {
                ull inr2[9];
#pragma unroll
                for (int c = 0; c < 9; c++)
                    inr2[c] = dup2(pb[(y + dy) * SP + x0 + c]);
#pragma unroll
                for (int dx = 0; dx < 3; dx++) {
                    int k = dy * 3 + dx;
#pragma unroll
                    for (int cp = 0; cp < 2; cp++) {
                        ull wk = wsm2[(cp * 32 + ic) * 9 + k];
#pragma unroll
                        for (int px = 0; px < 7; px++)
                            acc[cp][px] = ffma2(inr2[px + dx], wk, acc[cp][px]);
                    }
                }
            }
        }
    }
    if (active) {
#pragma unroll
        for (int cp = 0; cp < 2; cp++) {
            float* o0 = out + ((size_t)n * DCH + cobase + 2 * cp) * SS + y * S + x0;
            float* o1 = o0 + SS;
#pragma unroll
            for (int px = 0; px < 7; px++) {
                float2 f = unpack2(acc[cp][px]);
                o0[px] = f.x;
                o1[px] = f.y;
            }
        }
    }
}

// ---------------------------------------------------------------------------
// conv 64->64 @21, f32x2, K-split halves, TWO images per block (128 thr),
// 2 co-pairs per thread (4 output channels per block). grid (16, 40, 2).
// STAGE: 1 buf4 -> buf5/5b, 2 buf6 -> buf7/7b
// ---------------------------------------------------------------------------
template <int STAGE>
__global__ __launch_bounds__(128)
void conv21_kernel(const float* __restrict__ W) {
    constexpr int S = S3, SP = S + 2, SPSP = SP * SP, SS = S * S;
    constexpr int STRIPS = S / 7, NPOS = STRIPS * S;   // 63
    const float* in = (STAGE == 1) ? g_buf4 : g_buf6;
    float* outA = (STAGE == 1) ? g_buf5 : g_buf7;
    float* outB = (STAGE == 1) ? g_buf5b : g_buf7b;

    __shared__ float plane[2][2][SPSP];   // [img][buf][...]
    __shared__ ull wsm2[2 * 32 * 9];

    int tid = threadIdx.x;
    int img = tid >> 6, ltid = tid & 63;
    int n = blockIdx.y * 2 + img;
    int ks = blockIdx.z;
    int ci0 = ks * 32;
    int cobase = blockIdx.x * 4;
    float* out = ks ? outB : outA;

    for (int i = tid; i < 2 * 32 * 9; i += 128) {
        int cp = i / 288, rem = i % 288;
        int ic = rem / 9, k = rem % 9;
        float w0 = W[(cobase + cp * 2) * 576 + (ci0 + ic) * 9 + k];
        float w1 = W[(cobase + cp * 2 + 1) * 576 + (ci0 + ic) * 9 + k];
        wsm2[i] = pack2(w0, w1);
    }

    bool active = ltid < NPOS;
    int y = ltid / STRIPS, x0 = (ltid % STRIPS) * 7;

    ull acc[2][7];
#pragma unroll
    for (int cp = 0; cp < 2; cp++)
#pragma unroll
        for (int px = 0; px < 7; px++) acc[cp][px] = 0ull;

    const float* ibase = in + (size_t)n * DCH * SS + (size_t)ci0 * SS;

    for (int i = ltid; i < SPSP; i += 64) {
        int yy = i / SP - 1, xx = i % SP - 1;
        plane[img][0][i] = ((unsigned)yy < S && (unsigned)xx < S)
                               ? ibase[yy * S + xx] : 0.f;
    }

    for (int ic = 0; ic < 32; ic++) {
        __syncthreads();
        if (ic + 1 < 32) {
            const float* src = ibase + (ic + 1) * SS;
            int bidx = (ic + 1) & 1;
            for (int i = ltid; i < SPSP; i += 64) {
                int yy = i / SP - 1, xx = i % SP - 1;
                plane[img][bidx][i] = ((unsigned)yy < S && (unsigned)xx < S)
                                          ? src[yy * S + xx] : 0.f;
            }
        }
        if (active) {
            const float* pb = plane[img][ic & 1];
#pragma unroll
            for (int dy = 0; dy < 3; dy++) {
                ull inr2[9];
#pragma unroll
                for (int c = 0; c < 9; c++)
                    inr2[c] = dup2(pb[(y + dy) * SP + x0 + c]);
#pragma unroll
                for (int dx = 0; dx < 3; dx++) {
                    int k = dy * 3 + dx;
#pragma unroll
                    for (int cp = 0; cp < 2; cp++) {
                        ull wk = wsm2[(cp * 32 + ic) * 9 + k];
#pragma unroll
                        for (int px = 0; px < 7; px++)
                            acc[cp][px] = ffma2(inr2[px + dx], wk, acc[cp][px]);
                    }
                }
            }
        }
    }
    if (active) {
#pragma unroll
        for (int cp = 0; cp < 2; cp++) {
            float* o0 = out + ((size_t)n * DCH + cobase + 2 * cp) * SS + y * S + x0;
            float* o1 = o0 + SS;
#pragma unroll
            for (int px = 0; px < 7; px++) {
                float2 f = unpack2(acc[cp][px]);
                o0[px] = f.x;
                o1[px] = f.y;
            }
        }
    }
}

// ---------------------------------------------------------------------------
// BN partial stats -> g_stat[STAGE] via atomics (split stages merge partials).
// ---------------------------------------------------------------------------
template <int STAGE>
__global__ void bn_stats_part_kernel() {
    const float* inA = (STAGE == 0) ? g_buf1 : (STAGE == 1) ? g_buf3
                     : (STAGE == 2) ? g_buf5 : g_buf7;
    const float* inB = (STAGE == 1) ? g_buf3b
                     : (STAGE == 2) ? g_buf5b
                     : (STAGE == 3) ? g_buf7b : (const float*)0;
    const int S = (STAGE == 0) ? S1 : (STAGE == 1) ? S2 : S3;
    int ch  = blockIdx.x;
    int grp = blockIdx.y;
    int z   = blockIdx.z;
    int NS  = gridDim.z;
    int n0 = grp ? NQIMG : 0;
    int cnt = grp ? (NIMG - NQIMG) : NQIMG;
    int SS = S * S;
    long total = (long)cnt * SS;
    long len = (total + NS - 1) / NS;
    long i0 = (long)z * len;
    long i1 = min(total, i0 + len);
    float sum = 0.f, sumsq = 0.f;
    for (long i = i0 + threadIdx.x; i < i1; i += blockDim.x) {
        int n = n0 + (int)(i / SS);
        int p = (int)(i % SS);
        size_t idx = ((size_t)n * DCH + ch) * SS + p;
        float v = inA[idx];
        if (STAGE != 0) v += inB[idx];
        sum += v;
        sumsq += v * v;
    }
    __shared__ float s1[256], s2[256];
    int tid = threadIdx.x;
    s1[tid] = sum; s2[tid] = sumsq;
    __syncthreads();
    for (int off = 128; off > 0; off >>= 1) {
        if (tid < off) { s1[tid] += s1[tid + off]; s2[tid] += s2[tid + off]; }
        __syncthreads();
    }
    if (tid == 0) {
        atomicAdd(&g_stat[STAGE][grp][ch][0], s1[0]);
        atomicAdd(&g_stat[STAGE][grp][ch][1], s2[0]);
    }
}

// ---------------------------------------------------------------------------
// BN(inline A/C) + LeakyReLU + 2x2 maxpool.
// STAGE 0: buf1(84)->buf2(42). STAGE 1: (buf3+buf3b)(42)->buf4(21).
// ---------------------------------------------------------------------------
template <int STAGE>
__global__ __launch_bounds__(256)
void bn_pool_kernel(const float* __restrict__ g, const float* __restrict__ b) {
    const float* inA = (STAGE == 0) ? g_buf1 : g_buf3;
    const float* inB = (STAGE == 0) ? (const float*)0 : g_buf3b;
    float*      out = (STAGE == 0) ? g_buf2 : g_buf4;
    const int S  = (STAGE == 0) ? S1 : S2;
    const int So = S / 2;
    __shared__ float sA[128], sC[128];
    if (threadIdx.x < 128) {
        float2 ac = bn_ac<STAGE>(threadIdx.x >> 6, threadIdx.x & 63, g, b);
        sA[threadIdx.x] = ac.x; sC[threadIdx.x] = ac.y;
    }
    __syncthreads();
    long total = (long)NIMG * DCH * So * So;
    long idx = (long)blockIdx.x * blockDim.x + threadIdx.x;
    if (idx >= total) return;
    int SoSo = So * So;
    int p  = (int)(idx % SoSo);
    long t = idx / SoSo;
    int ch = (int)(t % DCH);
    int n  = (int)(t / DCH);
    int gi = ((n < NQIMG) ? 0 : 64) + ch;
    float a = sA[gi], c = sC[gi];
    int yo = p / So, xo = p % So;
    size_t base = ((size_t)n * DCH + ch) * S * S;
    float m = -1e30f;
#pragma unroll
    for (int dy = 0; dy < 2; dy++)
#pragma unroll
        for (int dx = 0; dx < 2; dx++) {
            size_t q = base + (2 * yo + dy) * S + (2 * xo + dx);
            float x = inA[q];
            if (STAGE != 0) x += inB[q];
            float v = x * a + c;
            v = (v > 0.f) ? v : LRELU_SLOPE * v;
            m = fmaxf(m, v);
        }
    out[idx] = m;
}

// ---------------------------------------------------------------------------
// BN(stage2) + LeakyReLU: (buf5+buf5b) -> buf6, S=21.
// ---------------------------------------------------------------------------
__global__ __launch_bounds__(256)
void bn_act_kernel(const float* __restrict__ g, const float* __restrict__ b) {
    __shared__ float sA[128], sC[128];
    if (threadIdx.x < 128) {
        float2 ac = bn_ac<2>(threadIdx.x >> 6, threadIdx.x & 63, g, b);
        sA[threadIdx.x] = ac.x; sC[threadIdx.x] = ac.y;
    }
    __syncthreads();
    long total = (long)NIMG * DCH * HW3;
    long idx = (long)blockIdx.x * blockDim.x + threadIdx.x;
    if (idx >= total) return;
    long t = idx / HW3;
    int ch = (int)(t % DCH);
    int n  = (int)(t / DCH);
    int gi = ((n < NQIMG) ? 0 : 64) + ch;
    float v = (g_buf5[idx] + g_buf5b[idx]) * sA[gi] + sC[gi];
    g_buf6[idx] = (v > 0.f) ? v : LRELU_SLOPE * v;
}

// ---------------------------------------------------------------------------
// Fused: BN(stage3) + LeakyReLU + L2-normalize + bf16 scatter. (buf7+buf7b)
// ---------------------------------------------------------------------------
__global__ __launch_bounds__(160)
void bn_norm_kernel(const float* __restrict__ g, const float* __restrict__ b) {
    int n = blockIdx.x;
    int l = blockIdx.y * 147 + threadIdx.x;
    int grp = (n < NQIMG) ? 0 : 1;
    __shared__ float sA[64], sC[64];
    if (threadIdx.x < 64) {
        float2 ac = bn_ac<3>(grp, threadIdx.x, g, b);
        sA[threadIdx.x] = ac.x; sC[threadIdx.x] = ac.y;
    }
    __syncthreads();
    if (threadIdx.x >= 147 || l >= HW3) return;

    const float* pa = g_buf7  + (size_t)n * DCH * HW3 + l;
    const float* pb = g_buf7b + (size_t)n * DCH * HW3 + l;
    float v[64];
    float ss = 0.f;
#pragma unroll
    for (int ch = 0; ch < 64; ch++) {
        float x = (pa[ch * HW3] + pb[ch * HW3]) * sA[ch] + sC[ch];
        x = (x > 0.f) ? x : LRELU_SLOPE * x;
        v[ch] = x;
        ss += x * x;
    }
    float inv = 1.f / fmaxf(sqrtf(ss), 1e-12f);

    __nv_bfloat16* dst;
    if (n < NQIMG) {
        dst = g_qbf + ((size_t)n * QPAD + l) * DCH;
    } else {
        int sn = n - NQIMG;
        int bb = sn / 25;
        int w  = (sn % 25) / 5;
        int sh = sn % 5;
        int sw = bb * 5 + w;
        int m  = sh * HW3 + l;
        dst = g_sbf + ((size_t)sw * SPAD + m) * DCH;
    }
#pragma unroll
    for (int c8 = 0; c8 < 64; c8 += 8) {
        uint4 u;
        u.x = bf2pack(v[c8 + 0] * inv, v[c8 + 1] * inv);
        u.y = bf2pack(v[c8 + 2] * inv, v[c8 + 3] * inv);
        u.z = bf2pack(v[c8 + 4] * inv, v[c8 + 5] * inv);
        u.w = bf2pack(v[c8 + 6] * inv, v[c8 + 7] * inv);
        *(uint4*)(dst + c8) = u;
    }
}

// ---------------------------------------------------------------------------
// Tensor-core similarity + fused top-3 + sum. (proven)
// ---------------------------------------------------------------------------
__global__ __launch_bounds__(512)
void sim_mma_kernel(float* __restrict__ out) {
    int mblk = blockIdx.x;
    int w    = blockIdx.y;
    int bq   = blockIdx.z;
    int sw   = (bq / 15) * 5 + w;
    int tid  = threadIdx.x;
    int warp = tid >> 5, lane = tid & 31;
    int g = lane >> 2, tg = lane & 3;

    int m0 = mblk * 256 + warp * 16;
    int r0 = m0 + g, r1 = r0 + 8;

    const __nv_bfloat16* qb = g_qbf + (size_t)bq * QPAD * DCH;
    u32 af[4][4];
#pragma unroll
    for (int kc = 0; kc < 4; kc++) {
        int c0 = kc * 16 + tg * 2;
        af[kc][0] = *(const u32*)(qb + (size_t)r0 * DCH + c0);
        af[kc][1] = *(const u32*)(qb + (size_t)r1 * DCH + c0);
        af[kc][2] = *(const u32*)(qb + (size_t)r0 * DCH + c0 + 8);
        af[kc][3] = *(const u32*)(qb + (size_t)r1 * DCH + c0 + 8);
    }

    float t0a = -1e30f, t1a = -1e30f, t2a = -1e30f;
    float t0b = -1e30f, t1b = -1e30f, t2b = -1e30f;

    __shared__ uint4 ssm[256 * 8];
    const uint4* sp = (const uint4*)(g_sbf + (size_t)sw * SPAD * DCH);

    for (int ch = 0; ch < 9; ch++) {
        __syncthreads();
        for (int i = tid; i < 2048; i += 512) {
            int nn = i >> 3, j = i & 7;
            ssm[(nn << 3) + (j ^ (nn & 7))] = sp[ch * 2048 + i];
        }
        __syncthreads();
        int nbase_ch = ch * 256;
        int tmax = (ch == 8) ? 20 : 32;
        for (int t = 0; t < tmax; t++) {
            int nl = (t << 3) + g;
            const u32* srow = (const u32*)ssm + ((size_t)nl << 5);
            float c0 = 0.f, c1 = 0.f, c2 = 0.f, c3 = 0.f;
#pragma unroll
            for (int kc = 0; kc < 4; kc++) {
                u32 b0 = srow[(((kc * 2)     ^ g) << 2) + tg];
                u32 b1 = srow[(((kc * 2 + 1) ^ g) << 2) + tg];
                asm volatile(
                    "mma.sync.aligned.m16n8k16.row.col.f32.bf16.bf16.f32 "
                    "{%0,%1,%2,%3}, {%4,%5,%6,%7}, {%8,%9}, {%0,%1,%2,%3};"
                    : "+f"(c0), "+f"(c1), "+f"(c2), "+f"(c3)
                    : "r"(af[kc][0]), "r"(af[kc][1]), "r"(af[kc][2]), "r"(af[kc][3]),
                      "r"(b0), "r"(b1));
            }
            int col0 = nbase_ch + (t << 3) + tg * 2;
            if (col0 < MDIM)     { TOPK3(t0a, t1a, t2a, c0); TOPK3(t0b, t1b, t2b, c2); }
            if (col0 + 1 < MDIM) { TOPK3(t0a, t1a, t2a, c1); TOPK3(t0b, t1b, t2b, c3); }
        }
    }

#pragma unroll
    for (int d = 1; d < 4; d <<= 1) {
        float m0a = __shfl_xor_sync(0xffffffffu, t0a, d);
        float m1a = __shfl_xor_sync(0xffffffffu, t1a, d);
        float m2a = __shfl_xor_sync(0xffffffffu, t2a, d);
        TOPK3(t0a, t1a, t2a, m0a); TOPK3(t0a, t1a, t2a, m1a); TOPK3(t0a, t1a, t2a, m2a);
        float m0b = __shfl_xor_sync(0xffffffffu, t0b, d);
        float m1b = __shfl_xor_sync(0xffffffffu, t1b, d);
        float m2b = __shfl_xor_sync(0xffffffffu, t2b, d);
        TOPK3(t0b, t1b, t2b, m0b); TOPK3(t0b, t1b, t2b, m1b); TOPK3(t0b, t1b, t2b, m2b);
    }

    float v = 0.f;
    if (tg == 0) {
        if (r0 < HW3) v += t0a + t1a + t2a;
        if (r1 < HW3) v += t0b + t1b + t2b;
    }
#pragma unroll
    for (int off = 16; off > 0; off >>= 1)
        v += __shfl_down_sync(0xffffffffu, v, off);

    __shared__ float red[16];
    if (lane == 0) red[warp] = v;
    __syncthreads();
    if (warp == 0) {
        float x = (lane < 16) ? red[lane] : 0.f;
#pragma unroll
        for (int off = 8; off > 0; off >>= 1)
            x += __shfl_down_sync(0xffffffffu, x, off);
        if (lane == 0) atomicAdd(&out[bq * 5 + w], x);
    }
}

// ---------------------------------------------------------------------------
// Launcher
// ---------------------------------------------------------------------------
extern "C" void kernel_launch(void* const* d_in, const int* in_sizes, int n_in,
                              void* d_out, int out_size) {
    const float* query   = (const float*)d_in[0];
    const float* support = (const float*)d_in[1];
    const float* W1 = (const float*)d_in[2];
    const float* W2 = (const float*)d_in[3];
    const float* W3 = (const float*)d_in[4];
    const float* W4 = (const float*)d_in[5];
    const float* g1 = (const float*)d_in[6];
    const float* b1 = (const float*)d_in[7];
    const float* g2 = (const float*)d_in[8];
    const float* b2 = (const float*)d_in[9];
    const float* g3 = (const float*)d_in[10];
    const float* b3 = (const float*)d_in[11];
    const float* g4 = (const float*)d_in[12];
    const float* b4 = (const float*)d_in[13];
    float* out = (float*)d_out;

    zero_misc_kernel<<<1, 1024>>>(out);

    // layer 1: conv 3->64 @84, stats, bn+lrelu+pool -> 42
    conv1_kernel<<<dim3(4, 80), 256>>>(query, support, W1);
    bn_stats_part_kernel<0><<<dim3(64, 2, 8), 256>>>();
    {
        long total = (long)NIMG * DCH * S2 * S2;
        bn_pool_kernel<0><<<(int)((total + 255) / 256), 256>>>(g1, b1);
    }
    // layer 2: f32x2 conv @42 (K-split, 4 co/block), stats, bn+lrelu+pool -> 21
    conv42_kernel<<<dim3(16, 80, 2), 256>>>(W2);
    bn_stats_part_kernel<1><<<dim3(64, 2, 4), 256>>>();
    {
        long total = (long)NIMG * DCH * S3 * S3;
        bn_pool_kernel<1><<<(int)((total + 255) / 256), 256>>>(g2, b2);
    }
    // layer 3: f32x2 conv @21 (K-split, 2-img, 4 co/block), stats, bn+lrelu
    conv21_kernel<1><<<dim3(16, 40, 2), 128>>>(W3);
    bn_stats_part_kernel<2><<<dim3(64, 2, 2), 256>>>();
    {
        long total = (long)NIMG * DCH * HW3;
        bn_act_kernel<<<(int)((total + 255) / 256), 256>>>(g3, b3);
    }
    // layer 4: f32x2 conv @21, stats, fused bn+norm+scatter
    conv21_kernel<2><<<dim3(16, 40, 2), 128>>>(W4);
    bn_stats_part_kernel<3><<<dim3(64, 2, 2), 256>>>();
    bn_norm_kernel<<<dim3(80, 3), 160>>>(g4, b4);
    // tensor-core similarity
    sim_mma_kernel<<<dim3(2, 5, 30), 512>>>(out);
}